// round 7
// baseline (speedup 1.0000x reference)
#include <cuda_runtime.h>
#include <cuda_bf16.h>
#include <math.h>
#include <stdint.h>

#define S    512
#define DIM  2048
#define H    32
#define HK   4
#define HD   128
#define NQK  (H*HD)    // 4096
#define NKV  (HK*HD)   // 512
#define NE   64
#define TOPK 8
#define FF   768
#define EPS  1e-6f
#define GRP  (H/HK)    // 8

// GEMM tile config: BM=64, BN=128, BK=32, 256 threads (8 warps, warp tile 32x32)
#define AW 20   // smem words per row (16 data + 4 pad) -> conflict-free frag LDS

// ---------------- scratch (static device globals; no allocation) -------------
__device__ float g_xn[S*DIM];
__device__ float g_qt[(size_t)H*S*HD];      // [h][s][d]
__device__ float g_kt[(size_t)HK*S*HD];     // [h][s][d]
__device__ float g_vtT[(size_t)HK*HD*S];    // [h][d][s]  (transposed for PV)
__device__ float g_scores[(size_t)H*S*S];
__device__ float g_attn[S*NQK];             // [s][h*HD+d]
__device__ float g_hn[S*DIM];
__device__ float g_midg[(size_t)NE*S*FF];
__device__ float g_midu[(size_t)NE*S*FF];
__device__ int   g_ecnt[NE];
__device__ int   g_etok[NE*S];
__device__ float g_ew  [NE*S];

// ---------------- helpers ----------------------------------------------------
struct SmemBuf {
    uint32_t Ahi[64*AW];
    uint32_t Alo[64*AW];
    uint32_t Bhi[128*AW];
    uint32_t Blo[128*AW];
};  // 30720 bytes
#define DSMEM_BYTES (2 * (int)sizeof(SmemBuf))   // 61440

__device__ __forceinline__ void mma16816(float* c, const uint32_t* a, const uint32_t* b) {
    asm volatile(
        "mma.sync.aligned.m16n8k16.row.col.f32.bf16.bf16.f32 "
        "{%0,%1,%2,%3}, {%4,%5,%6,%7}, {%8,%9}, {%0,%1,%2,%3};"
        : "+f"(c[0]), "+f"(c[1]), "+f"(c[2]), "+f"(c[3])
        : "r"(a[0]), "r"(a[1]), "r"(a[2]), "r"(a[3]), "r"(b[0]), "r"(b[1]));
}

// hi = truncate-to-bf16 (top 16 bits, packed via PRMT), lo = bf16_rn(x - hi)
__device__ __forceinline__ void pack_hl(float a, float b, uint32_t& hi, uint32_t& lo) {
    uint32_t ab = __float_as_uint(a), bb = __float_as_uint(b);
    hi = __byte_perm(ab, bb, 0x7632);
    float ah = __uint_as_float(ab & 0xFFFF0000u);
    float bh = __uint_as_float(bb & 0xFFFF0000u);
    __nv_bfloat162 l = __floats2bfloat162_rn(a - ah, b - bh);
    lo = *reinterpret_cast<uint32_t*>(&l);
}

__device__ __forceinline__ void cvt_store(SmemBuf& s, int awBase, int bwBase,
                                          const float4* va, const float4* vb) {
    #pragma unroll
    for (int j = 0; j < 2; j++) {
        uint32_t h0, l0, h1, l1;
        pack_hl(va[j].x, va[j].y, h0, l0);
        pack_hl(va[j].z, va[j].w, h1, l1);
        *(uint2*)&s.Ahi[awBase + j*2] = make_uint2(h0, h1);
        *(uint2*)&s.Alo[awBase + j*2] = make_uint2(l0, l1);
    }
    #pragma unroll
    for (int j = 0; j < 4; j++) {
        uint32_t h0, l0, h1, l1;
        pack_hl(vb[j].x, vb[j].y, h0, l0);
        pack_hl(vb[j].z, vb[j].w, h1, l1);
        *(uint2*)&s.Bhi[bwBase + j*2] = make_uint2(h0, h1);
        *(uint2*)&s.Blo[bwBase + j*2] = make_uint2(l0, l1);
    }
}

__device__ __forceinline__ void mma_step(SmemBuf& s, int ks, int wm, int wn,
                                         int lane, float (&acc)[8][4]) {
    const int kw = ks * 8;
    uint32_t ah[2][4], al[2][4], bh[4][2], bl[4][2];
    #pragma unroll
    for (int mt = 0; mt < 2; mt++) {
        int r0 = (wm*32 + mt*16 + (lane>>2)) * AW + kw + (lane&3);
        int r1 = r0 + 8*AW;
        ah[mt][0] = s.Ahi[r0];     ah[mt][1] = s.Ahi[r1];
        ah[mt][2] = s.Ahi[r0+4];   ah[mt][3] = s.Ahi[r1+4];
        al[mt][0] = s.Alo[r0];     al[mt][1] = s.Alo[r1];
        al[mt][2] = s.Alo[r0+4];   al[mt][3] = s.Alo[r1+4];
    }
    #pragma unroll
    for (int nt = 0; nt < 4; nt++) {
        int n0 = (wn*32 + nt*8 + (lane>>2)) * AW + kw + (lane&3);
        bh[nt][0] = s.Bhi[n0];  bh[nt][1] = s.Bhi[n0+4];
        bl[nt][0] = s.Blo[n0];  bl[nt][1] = s.Blo[n0+4];
    }
    #pragma unroll
    for (int mt = 0; mt < 2; mt++)
        #pragma unroll
        for (int nt = 0; nt < 4; nt++) {
            mma16816(acc[mt*4+nt], ah[mt], bh[nt]);
            mma16816(acc[mt*4+nt], ah[mt], bl[nt]);
            mma16816(acc[mt*4+nt], al[mt], bh[nt]);
        }
}

// =============================================================================
// Core: C[64,128] = A[64,K] @ B[128 rows,K]^T, bf16 hi/lo split (3 passes),
// fp32 accum in registers. Double-buffered smem, one sync per 32-chunk.
// rowTok (smem, 64 ints) gathers A rows if non-null. K % 32 == 0.
// =============================================================================
__device__ __forceinline__ void mma_gemm(
    SmemBuf* sb,
    const float* __restrict__ A, int lda, const int* rowTok, int mBase,
    const float* __restrict__ B, int ldb, int nBase, int K,
    float (&acc)[8][4])
{
    const int tid  = threadIdx.x;
    const int lane = tid & 31, wid = tid >> 5;
    const int wm = wid >> 2, wn = wid & 3;

    const int rA = tid >> 2, qA = tid & 3;          // A: 64 rows x 8 floats
    const int rB = tid >> 1, hB = tid & 1;          // B: 128 rows x 16 floats
    const int rowA = rowTok ? rowTok[rA] : (mBase + rA);
    const float* Ap = A + (size_t)rowA * lda + qA * 8;
    const float* Bp = B + (size_t)(nBase + rB) * ldb + hB * 16;
    const int awBase = rA * AW + qA * 4;
    const int bwBase = rB * AW + hB * 8;
    const int nch = K >> 5;

    float4 va[2], vb[4];
    va[0] = *(const float4*)(Ap);
    va[1] = *(const float4*)(Ap + 4);
    #pragma unroll
    for (int j = 0; j < 4; j++) vb[j] = *(const float4*)(Bp + j * 4);
    cvt_store(sb[0], awBase, bwBase, va, vb);
    if (nch > 1) {
        va[0] = *(const float4*)(Ap + 32);
        va[1] = *(const float4*)(Ap + 36);
        #pragma unroll
        for (int j = 0; j < 4; j++) vb[j] = *(const float4*)(Bp + 32 + j * 4);
    }
    __syncthreads();

    for (int t = 0; t < nch; t++) {
        SmemBuf& cur = sb[t & 1];
        SmemBuf& nxt = sb[(t & 1) ^ 1];
        mma_step(cur, 0, wm, wn, lane, acc);
        if (t + 1 < nch) cvt_store(nxt, awBase, bwBase, va, vb);
        mma_step(cur, 1, wm, wn, lane, acc);
        if (t + 2 < nch) {
            va[0] = *(const float4*)(Ap + (t+2)*32);
            va[1] = *(const float4*)(Ap + (t+2)*32 + 4);
            #pragma unroll
            for (int j = 0; j < 4; j++)
                vb[j] = *(const float4*)(Bp + (t+2)*32 + j*4);
        }
        __syncthreads();
    }
}

// ---------------- small utility kernels --------------------------------------
__global__ void zero_counts_kernel() {
    if (threadIdx.x < NE) g_ecnt[threadIdx.x] = 0;
}

__global__ void rmsnorm_kernel(const float* __restrict__ x,
                               const float* __restrict__ w,
                               float* __restrict__ out) {
    int row = blockIdx.x;
    const float* xr = x + (size_t)row * DIM;
    float ss = 0.f;
    for (int i = threadIdx.x; i < DIM; i += 256) { float v = xr[i]; ss += v * v; }
    __shared__ float red[256];
    red[threadIdx.x] = ss; __syncthreads();
    for (int st = 128; st > 0; st >>= 1) {
        if (threadIdx.x < st) red[threadIdx.x] += red[threadIdx.x + st];
        __syncthreads();
    }
    float rstd = rsqrtf(red[0] / (float)DIM + EPS);
    for (int i = threadIdx.x; i < DIM; i += 256)
        out[(size_t)row * DIM + i] = xr[i] * rstd * w[i];
}

__global__ void qknorm_rope_kernel(const float* __restrict__ qnw,
                                   const float* __restrict__ knw,
                                   const float* __restrict__ cosp,
                                   const float* __restrict__ sinp)
{
    int s = blockIdx.x, h2 = blockIdx.y, d = threadIdx.x;   // 128 threads
    float* ptr; const float* w;
    if (h2 < H) { ptr = g_qt + (size_t)h2       * S * HD + (size_t)s * HD; w = qnw; }
    else        { ptr = g_kt + (size_t)(h2 - H) * S * HD + (size_t)s * HD; w = knw; }
    __shared__ float row[HD];
    __shared__ float red[HD];
    float v = ptr[d];
    red[d] = v * v; __syncthreads();
    for (int st = 64; st > 0; st >>= 1) {
        if (d < st) red[d] += red[d + st];
        __syncthreads();
    }
    float rstd = rsqrtf(red[0] / (float)HD + EPS);
    row[d] = v * rstd * w[d];
    __syncthreads();
    float rot = (d < 64) ? -row[d + 64] : row[d - 64];
    ptr[d] = row[d] * cosp[s * HD + d] + rot * sinp[s * HD + d];
}

__global__ void softmax_kernel()
{
    int s = blockIdx.x, h = blockIdx.y, tid = threadIdx.x;   // 128 threads
    float* row = g_scores + (size_t)h * S * S + (size_t)s * S;
    int nk = s + 1;
    __shared__ float red[128];
    float m = -1e30f;
    for (int i = tid; i < nk; i += 128) m = fmaxf(m, row[i]);
    red[tid] = m; __syncthreads();
    for (int st = 64; st > 0; st >>= 1) {
        if (tid < st) red[tid] = fmaxf(red[tid], red[tid + st]);
        __syncthreads();
    }
    m = red[0]; __syncthreads();
    float sum = 0.f;
    for (int i = tid; i < nk; i += 128) {
        float e = expf(row[i] - m);
        row[i] = e; sum += e;
    }
    red[tid] = sum; __syncthreads();
    for (int st = 64; st > 0; st >>= 1) {
        if (tid < st) red[tid] += red[tid + st];
        __syncthreads();
    }
    float inv = 1.f / red[0];
    for (int i = tid; i < nk; i += 128) row[i] *= inv;
    for (int i = nk + tid; i < S; i += 128) row[i] = 0.f;
}

__global__ void router_kernel(const float* __restrict__ rw)
{
    int t = blockIdx.x, tid = threadIdx.x;   // 128 threads
    __shared__ float hrow[DIM];
    __shared__ float logits[NE];
    for (int i = tid; i < DIM; i += 128) hrow[i] = g_hn[(size_t)t * DIM + i];
    __syncthreads();
    if (tid < NE) {
        const float* r = rw + (size_t)tid * DIM;
        float acc = 0.f;
        for (int i = 0; i < DIM; i++) acc += hrow[i] * r[i];
        logits[tid] = acc;
    }
    __syncthreads();
    if (tid == 0) {
        float m = -1e30f;
        for (int e = 0; e < NE; e++) m = fmaxf(m, logits[e]);
        float pr[NE]; float sum = 0.f;
        for (int e = 0; e < NE; e++) { pr[e] = expf(logits[e] - m); sum += pr[e]; }
        float invs = 1.f / sum;
        for (int e = 0; e < NE; e++) pr[e] *= invs;
        int   ti[TOPK]; float tw[TOPK]; float wsum = 0.f;
        for (int kk = 0; kk < TOPK; kk++) {
            int best = 0; float bv = -1.f;
            for (int e = 0; e < NE; e++) if (pr[e] > bv) { bv = pr[e]; best = e; }
            ti[kk] = best; tw[kk] = bv; pr[best] = -2.f; wsum += bv;
        }
        float inv = 1.f / (wsum + 1e-20f);
        for (int kk = 0; kk < TOPK; kk++) {
            int e = ti[kk];
            int pos = atomicAdd(&g_ecnt[e], 1);
            g_etok[e * S + pos] = t;
            g_ew  [e * S + pos] = tw[kk] * inv;
        }
    }
}

__global__ void silu_kernel()
{
    int slot = blockIdx.x, e = blockIdx.y;
    if (slot >= g_ecnt[e]) return;
    size_t base = (size_t)(e * S + slot) * FF;
    for (int i = threadIdx.x; i < FF; i += 256) {
        float g = g_midg[base + i], u = g_midu[base + i];
        g_midg[base + i] = g / (1.f + expf(-g)) * u;
    }
}

// ================== HMMA GEMM kernels =========================================

// QKV: grid (40, 8). x<32: q head; [32,36): k head; [36,40): v head (-> V^T).
__global__ __launch_bounds__(256) void qkv_kernel(
    const float* __restrict__ xn, const float* __restrict__ wq,
    const float* __restrict__ wk, const float* __restrict__ wv)
{
    extern __shared__ SmemBuf sb[];
    int nt = blockIdx.x, mBase = blockIdx.y * 64;
    const float* B; int head, fam;
    if (nt < H)           { B = wq; head = nt;          fam = 0; }
    else if (nt < H + HK) { B = wk; head = nt - H;      fam = 1; }
    else                  { B = wv; head = nt - H - HK; fam = 2; }
    float acc[8][4] = {};
    mma_gemm(sb, xn, DIM, nullptr, mBase, B, DIM, head * HD, DIM, acc);
    int lane = threadIdx.x & 31, wid = threadIdx.x >> 5;
    int wm = wid >> 2, wn = wid & 3;
    #pragma unroll
    for (int mt = 0; mt < 2; mt++)
        #pragma unroll
        for (int ntl = 0; ntl < 4; ntl++) {
            int r0  = mBase + wm*32 + mt*16 + (lane>>2);
            int col = wn*32 + ntl*8 + (lane&3)*2;
            float* a = acc[mt*4+ntl];
            if (fam == 0) {
                float* o = g_qt + (size_t)head*S*HD;
                *(float2*)&o[(size_t)r0*HD + col]     = make_float2(a[0], a[1]);
                *(float2*)&o[(size_t)(r0+8)*HD + col] = make_float2(a[2], a[3]);
            } else if (fam == 1) {
                float* o = g_kt + (size_t)head*S*HD;
                *(float2*)&o[(size_t)r0*HD + col]     = make_float2(a[0], a[1]);
                *(float2*)&o[(size_t)(r0+8)*HD + col] = make_float2(a[2], a[3]);
            } else {
                float* o = g_vtT + (size_t)head*HD*S;
                o[(size_t)col*S     + r0]     = a[0];
                o[(size_t)(col+1)*S + r0]     = a[1];
                o[(size_t)col*S     + r0 + 8] = a[2];
                o[(size_t)(col+1)*S + r0 + 8] = a[3];
            }
        }
}

// scores: grid (4, 8, 32). Skip fully-masked tiles.
__global__ __launch_bounds__(256) void scores_kernel()
{
    int h = blockIdx.z, mBase = blockIdx.y * 64, nBase = blockIdx.x * 128;
    if (nBase > mBase + 63) return;
    extern __shared__ SmemBuf sb[];
    int kvh = h / GRP;
    float acc[8][4] = {};
    mma_gemm(sb, g_qt + (size_t)h * S * HD, HD, nullptr, mBase,
             g_kt + (size_t)kvh * S * HD, HD, nBase, HD, acc);
    const float alpha = 0.08838834764831845f;   // 1/sqrt(128)
    float* C = g_scores + (size_t)h * S * S;
    int lane = threadIdx.x & 31, wid = threadIdx.x >> 5;
    int wm = wid >> 2, wn = wid & 3;
    #pragma unroll
    for (int mt = 0; mt < 2; mt++)
        #pragma unroll
        for (int ntl = 0; ntl < 4; ntl++) {
            int r0  = mBase + wm*32 + mt*16 + (lane>>2);
            int col = nBase + wn*32 + ntl*8 + (lane&3)*2;
            float* a = acc[mt*4+ntl];
            *(float2*)&C[(size_t)r0*S + col]     = make_float2(a[0]*alpha, a[1]*alpha);
            *(float2*)&C[(size_t)(r0+8)*S + col] = make_float2(a[2]*alpha, a[3]*alpha);
        }
}

// pv: grid (1, 8, 32). A = softmaxed scores, B = V^T.
__global__ __launch_bounds__(256) void pv_kernel()
{
    extern __shared__ SmemBuf sb[];
    int h = blockIdx.z, mBase = blockIdx.y * 64;
    int kvh = h / GRP;
    float acc[8][4] = {};
    mma_gemm(sb, g_scores + (size_t)h * S * S, S, nullptr, mBase,
             g_vtT + (size_t)kvh * HD * S, S, 0, S, acc);
    int lane = threadIdx.x & 31, wid = threadIdx.x >> 5;
    int wm = wid >> 2, wn = wid & 3;
    #pragma unroll
    for (int mt = 0; mt < 2; mt++)
        #pragma unroll
        for (int ntl = 0; ntl < 4; ntl++) {
            int r0  = mBase + wm*32 + mt*16 + (lane>>2);
            int col = h*HD + wn*32 + ntl*8 + (lane&3)*2;
            float* a = acc[mt*4+ntl];
            *(float2*)&g_attn[(size_t)r0*NQK + col]     = make_float2(a[0], a[1]);
            *(float2*)&g_attn[(size_t)(r0+8)*NQK + col] = make_float2(a[2], a[3]);
        }
}

// wo: grid (16, 8). out = attn @ wo^T + x  -> d_out
__global__ __launch_bounds__(256) void wo_kernel(
    const float* __restrict__ wo_w, const float* __restrict__ x,
    float* __restrict__ out)
{
    extern __shared__ SmemBuf sb[];
    int nBase = blockIdx.x * 128, mBase = blockIdx.y * 64;
    float acc[8][4] = {};
    mma_gemm(sb, g_attn, NQK, nullptr, mBase, wo_w, NQK, nBase, NQK, acc);
    int lane = threadIdx.x & 31, wid = threadIdx.x >> 5;
    int wm = wid >> 2, wn = wid & 3;
    #pragma unroll
    for (int mt = 0; mt < 2; mt++)
        #pragma unroll
        for (int ntl = 0; ntl < 4; ntl++) {
            int r0  = mBase + wm*32 + mt*16 + (lane>>2);
            int col = nBase + wn*32 + ntl*8 + (lane&3)*2;
            float* a = acc[mt*4+ntl];
            size_t i0 = (size_t)r0*DIM + col, i1 = (size_t)(r0+8)*DIM + col;
            float2 x0 = *(const float2*)&x[i0], x1 = *(const float2*)&x[i1];
            *(float2*)&out[i0] = make_float2(a[0] + x0.x, a[1] + x0.y);
            *(float2*)&out[i1] = make_float2(a[2] + x1.x, a[3] + x1.y);
        }
}

// moe mid: grid (12, 8, 64). x<6 gate, else up. Gathered A rows.
__global__ __launch_bounds__(256) void moe_mid_kernel(
    const float* __restrict__ gate_w, const float* __restrict__ up_w)
{
    int e = blockIdx.z;
    int Me = g_ecnt[e];
    int rowBase = blockIdx.y * 64;
    if (rowBase >= Me) return;
    extern __shared__ SmemBuf sb[];
    __shared__ int tok[64];
    if (threadIdx.x < 64)
        tok[threadIdx.x] = g_etok[e * S + min(rowBase + (int)threadIdx.x, Me - 1)];
    __syncthreads();
    int xt = blockIdx.x;
    const float* B; float* C; int nBase;
    if (xt < 6) { B = gate_w + (size_t)e * FF * DIM; nBase = xt * 128;       C = g_midg; }
    else        { B = up_w   + (size_t)e * FF * DIM; nBase = (xt - 6) * 128; C = g_midu; }
    float acc[8][4] = {};
    mma_gemm(sb, g_hn, DIM, tok, 0, B, DIM, nBase, DIM, acc);
    int lane = threadIdx.x & 31, wid = threadIdx.x >> 5;
    int wm = wid >> 2, wn = wid & 3;
    #pragma unroll
    for (int mt = 0; mt < 2; mt++)
        #pragma unroll
        for (int ntl = 0; ntl < 4; ntl++) {
            int lr  = wm*32 + mt*16 + (lane>>2);
            int col = nBase + wn*32 + ntl*8 + (lane&3)*2;
            float* a = acc[mt*4+ntl];
            int s0 = rowBase + lr, s1 = s0 + 8;
            if (s0 < Me)
                *(float2*)&C[(size_t)(e*S + s0)*FF + col] = make_float2(a[0], a[1]);
            if (s1 < Me)
                *(float2*)&C[(size_t)(e*S + s1)*FF + col] = make_float2(a[2], a[3]);
        }
}

// moe down: grid (16, 8, 64). Weighted atomic scatter onto out.
__global__ __launch_bounds__(256) void moe_down_kernel(
    const float* __restrict__ down_w, float* __restrict__ out)
{
    int e = blockIdx.z;
    int Me = g_ecnt[e];
    int rowBase = blockIdx.y * 64;
    if (rowBase >= Me) return;
    extern __shared__ SmemBuf sb[];
    __shared__ int tok[64];
    __shared__ float wts[64];
    if (threadIdx.x < 64) {
        int sl = min(rowBase + (int)threadIdx.x, Me - 1);
        tok[threadIdx.x] = g_etok[e * S + sl];
        wts[threadIdx.x] = g_ew  [e * S + sl];
    }
    __syncthreads();
    int nBase = blockIdx.x * 128;
    float acc[8][4] = {};
    mma_gemm(sb, g_midg + (size_t)e * S * FF, FF, nullptr, rowBase,
             down_w + (size_t)e * DIM * FF, FF, nBase, FF, acc);
    int lane = threadIdx.x & 31, wid = threadIdx.x >> 5;
    int wm = wid >> 2, wn = wid & 3;
    #pragma unroll
    for (int mt = 0; mt < 2; mt++)
        #pragma unroll
        for (int ntl = 0; ntl < 4; ntl++) {
            int lr  = wm*32 + mt*16 + (lane>>2);
            int col = nBase + wn*32 + ntl*8 + (lane&3)*2;
            float* a = acc[mt*4+ntl];
            int s0 = rowBase + lr, s1 = s0 + 8;
            if (s0 < Me) {
                int t = tok[lr]; float w = wts[lr];
                atomicAdd(&out[(size_t)t*DIM + col],     a[0]*w);
                atomicAdd(&out[(size_t)t*DIM + col + 1], a[1]*w);
            }
            if (s1 < Me) {
                int t = tok[lr+8]; float w = wts[lr+8];
                atomicAdd(&out[(size_t)t*DIM + col],     a[2]*w);
                atomicAdd(&out[(size_t)t*DIM + col + 1], a[3]*w);
            }
        }
}

// ---------------- launch ------------------------------------------------------
extern "C" void kernel_launch(void* const* d_in, const int* in_sizes, int n_in,
                              void* d_out, int out_size)
{
    const float* x    = (const float*)d_in[0];
    const float* cosp = (const float*)d_in[1];
    const float* sinp = (const float*)d_in[2];
    const float* n1w  = (const float*)d_in[3];
    const float* wq   = (const float*)d_in[4];
    const float* wk   = (const float*)d_in[5];
    const float* wv   = (const float*)d_in[6];
    const float* wo_w = (const float*)d_in[7];
    const float* qnw  = (const float*)d_in[8];
    const float* knw  = (const float*)d_in[9];
    const float* n2w  = (const float*)d_in[10];
    const float* rw   = (const float*)d_in[11];
    const float* gw   = (const float*)d_in[12];
    const float* uw   = (const float*)d_in[13];
    const float* dw   = (const float*)d_in[14];
    float* out = (float*)d_out;

    static int attr_done = 0;
    if (!attr_done) {
        cudaFuncSetAttribute(qkv_kernel,      cudaFuncAttributeMaxDynamicSharedMemorySize, DSMEM_BYTES);
        cudaFuncSetAttribute(scores_kernel,   cudaFuncAttributeMaxDynamicSharedMemorySize, DSMEM_BYTES);
        cudaFuncSetAttribute(pv_kernel,       cudaFuncAttributeMaxDynamicSharedMemorySize, DSMEM_BYTES);
        cudaFuncSetAttribute(wo_kernel,       cudaFuncAttributeMaxDynamicSharedMemorySize, DSMEM_BYTES);
        cudaFuncSetAttribute(moe_mid_kernel,  cudaFuncAttributeMaxDynamicSharedMemorySize, DSMEM_BYTES);
        cudaFuncSetAttribute(moe_down_kernel, cudaFuncAttributeMaxDynamicSharedMemorySize, DSMEM_BYTES);
        attr_done = 1;
    }

    float *xn, *hn;
    cudaGetSymbolAddress((void**)&xn, g_xn);
    cudaGetSymbolAddress((void**)&hn, g_hn);

    zero_counts_kernel<<<1, 64>>>();
    rmsnorm_kernel<<<S, 256>>>(x, n1w, xn);
    qkv_kernel<<<dim3(H + 2*HK, S/64), 256, DSMEM_BYTES>>>(xn, wq, wk, wv);
    qknorm_rope_kernel<<<dim3(S, H + HK), HD>>>(qnw, knw, cosp, sinp);
    scores_kernel<<<dim3(S/128, S/64, H), 256, DSMEM_BYTES>>>();
    softmax_kernel<<<dim3(S, H), 128>>>();
    pv_kernel<<<dim3(1, S/64, H), 256, DSMEM_BYTES>>>();
    wo_kernel<<<dim3(DIM/128, S/64), 256, DSMEM_BYTES>>>(wo_w, x, out);
    rmsnorm_kernel<<<S, 256>>>(out, n2w, hn);
    router_kernel<<<S, 128>>>(rw);
    moe_mid_kernel<<<dim3(12, S/64, NE), 256, DSMEM_BYTES>>>(gw, uw);
    silu_kernel<<<dim3(S, NE), 256>>>();
    moe_down_kernel<<<dim3(DIM/128, S/64, NE), 256, DSMEM_BYTES>>>(dw, out);
}

// round 9
// speedup vs baseline: 1.8778x; 1.8778x over previous
#include <cuda_runtime.h>
#include <cuda_bf16.h>
#include <math.h>
#include <stdint.h>

#define S    512
#define DIM  2048
#define H    32
#define HK   4
#define HD   128
#define NQK  (H*HD)    // 4096
#define NKV  (HK*HD)   // 512
#define NE   64
#define TOPK 8
#define FF   768
#define EPS  1e-6f
#define GRP  (H/HK)    // 8

// GEMM tile config: BM=64, BN=128, BK=32, 256 threads (8 warps, warp tile 32x32)
#define AW 20   // smem words per row (16 data + 4 pad) -> conflict-free frag LDS

// ---------------- scratch (static device globals; no allocation) -------------
__device__ float g_xn[S*DIM];
__device__ float g_qt[(size_t)H*S*HD];      // [h][s][d]
__device__ float g_kt[(size_t)HK*S*HD];     // [h][s][d]
__device__ float g_vtT[(size_t)HK*HD*S];    // [h][d][s]  (transposed for PV)
__device__ float g_scores[(size_t)H*S*S];
__device__ float g_attn[S*NQK];             // [s][h*HD+d]
__device__ float g_hn[S*DIM];
__device__ float g_midg[(size_t)NE*S*FF];
__device__ float g_midu[(size_t)NE*S*FF];
__device__ int   g_ecnt[NE];
__device__ int   g_etok[NE*S];
__device__ float g_ew  [NE*S];

// ---------------- helpers ----------------------------------------------------
struct SmemT {
    uint32_t Ahi[64*AW];
    uint32_t Alo[64*AW];
    uint32_t Bhi[128*AW];
    uint32_t Blo[128*AW];
};

__device__ __forceinline__ uint32_t s2u(const void* p) {
    uint32_t a;
    asm("{ .reg .u64 t; cvta.to.shared.u64 t, %1; cvt.u32.u64 %0, t; }"
        : "=r"(a) : "l"(p));
    return a;
}

__device__ __forceinline__ void ldsm4(uint32_t* r, uint32_t addr) {
    asm volatile("ldmatrix.sync.aligned.m8n8.x4.shared.b16 {%0,%1,%2,%3}, [%4];"
                 : "=r"(r[0]), "=r"(r[1]), "=r"(r[2]), "=r"(r[3]) : "r"(addr));
}

__device__ __forceinline__ void mma16816(float* c, const uint32_t* a, const uint32_t* b) {
    asm volatile(
        "mma.sync.aligned.m16n8k16.row.col.f32.bf16.bf16.f32 "
        "{%0,%1,%2,%3}, {%4,%5,%6,%7}, {%8,%9}, {%0,%1,%2,%3};"
        : "+f"(c[0]), "+f"(c[1]), "+f"(c[2]), "+f"(c[3])
        : "r"(a[0]), "r"(a[1]), "r"(a[2]), "r"(a[3]), "r"(b[0]), "r"(b[1]));
}

__device__ __forceinline__ void pack_hl(float a, float b, uint32_t& hi, uint32_t& lo) {
    __nv_bfloat162 h = __floats2bfloat162_rn(a, b);
    float ah = __bfloat162float(h.x), bh = __bfloat162float(h.y);
    __nv_bfloat162 l = __floats2bfloat162_rn(a - ah, b - bh);
    hi = *reinterpret_cast<uint32_t*>(&h);
    lo = *reinterpret_cast<uint32_t*>(&l);
}

__device__ __forceinline__ void cvt_store(SmemT& s, int awBase, int bwBase,
                                          const float4* va, const float4* vb) {
    #pragma unroll
    for (int j = 0; j < 2; j++) {
        uint32_t h0, l0, h1, l1;
        pack_hl(va[j].x, va[j].y, h0, l0);
        pack_hl(va[j].z, va[j].w, h1, l1);
        *(uint2*)&s.Ahi[awBase + j*2] = make_uint2(h0, h1);
        *(uint2*)&s.Alo[awBase + j*2] = make_uint2(l0, l1);
    }
    #pragma unroll
    for (int j = 0; j < 4; j++) {
        uint32_t h0, l0, h1, l1;
        pack_hl(vb[j].x, vb[j].y, h0, l0);
        pack_hl(vb[j].z, vb[j].w, h1, l1);
        *(uint2*)&s.Bhi[bwBase + j*2] = make_uint2(h0, h1);
        *(uint2*)&s.Blo[bwBase + j*2] = make_uint2(l0, l1);
    }
}

// fragment loads via ldmatrix; mappings verified against the scalar-load layout
__device__ __forceinline__ void mma_step(uint32_t aHiB, uint32_t aLoB,
                                         uint32_t bHiB, uint32_t bLoB,
                                         int ks, int wm, int wn, int lane,
                                         float (&acc)[8][4]) {
    const int kw = ks * 8;
    const int r = lane & 7, sub = lane >> 3;
    uint32_t ah[2][4], al[2][4], bh[2][4], bl[2][4];
    #pragma unroll
    for (int mt = 0; mt < 2; mt++) {
        uint32_t off = (uint32_t)(((wm*32 + mt*16 + r + (sub&1)*8) * AW
                                   + kw + (sub>>1)*4) * 4);
        ldsm4(ah[mt], aHiB + off);
        ldsm4(al[mt], aLoB + off);
    }
    #pragma unroll
    for (int p = 0; p < 2; p++) {
        uint32_t off = (uint32_t)(((wn*32 + p*16 + r + (sub>>1)*8) * AW
                                   + kw + (sub&1)*4) * 4);
        ldsm4(bh[p], bHiB + off);
        ldsm4(bl[p], bLoB + off);
    }
    #pragma unroll
    for (int mt = 0; mt < 2; mt++)
        #pragma unroll
        for (int nt = 0; nt < 4; nt++) {
            uint32_t bh2[2] = { bh[nt>>1][(nt&1)*2], bh[nt>>1][(nt&1)*2+1] };
            uint32_t bl2[2] = { bl[nt>>1][(nt&1)*2], bl[nt>>1][(nt&1)*2+1] };
            mma16816(acc[mt*4+nt], ah[mt], bh2);
            mma16816(acc[mt*4+nt], ah[mt], bl2);
            mma16816(acc[mt*4+nt], al[mt], bh2);
        }
}

// =============================================================================
// Core: C[64,128] = A[64,K] @ B[128 rows,K]^T, bf16 hi/lo split (3 passes),
// fp32 accum in registers. Single smem buffer (R6 structure, 2 CTAs/SM).
// rowTok (smem, 64 ints) gathers A rows if non-null. K % 32 == 0.
// =============================================================================
__device__ __forceinline__ void mma_gemm(
    SmemT& sm,
    const float* __restrict__ A, int lda, const int* rowTok, int mBase,
    const float* __restrict__ B, int ldb, int nBase, int K,
    float (&acc)[8][4])
{
    const int tid  = threadIdx.x;
    const int lane = tid & 31, wid = tid >> 5;
    const int wm = wid >> 2, wn = wid & 3;

    const int rA = tid >> 2, qA = tid & 3;          // A: 64 rows x 8 floats
    const int rB = tid >> 1, hB = tid & 1;          // B: 128 rows x 16 floats
    const int rowA = rowTok ? rowTok[rA] : (mBase + rA);
    const float* Ap = A + (size_t)rowA * lda + qA * 8;
    const float* Bp = B + (size_t)(nBase + rB) * ldb + hB * 16;

    float4 va[2], vb[4];
    va[0] = *(const float4*)(Ap);
    va[1] = *(const float4*)(Ap + 4);
    #pragma unroll
    for (int j = 0; j < 4; j++) vb[j] = *(const float4*)(Bp + j * 4);

    const int nch = K >> 5;
    const int awBase = rA * AW + qA * 4;
    const int bwBase = rB * AW + hB * 8;
    const uint32_t aHiB = s2u(sm.Ahi), aLoB = s2u(sm.Alo);
    const uint32_t bHiB = s2u(sm.Bhi), bLoB = s2u(sm.Blo);

    for (int t = 0; t < nch; t++) {
        cvt_store(sm, awBase, bwBase, va, vb);
        __syncthreads();

        if (t + 1 < nch) {   // prefetch next chunk
            va[0] = *(const float4*)(Ap + (t+1)*32);
            va[1] = *(const float4*)(Ap + (t+1)*32 + 4);
            #pragma unroll
            for (int j = 0; j < 4; j++)
                vb[j] = *(const float4*)(Bp + (t+1)*32 + j*4);
        }

        mma_step(aHiB, aLoB, bHiB, bLoB, 0, wm, wn, lane, acc);
        mma_step(aHiB, aLoB, bHiB, bLoB, 1, wm, wn, lane, acc);
        __syncthreads();
    }
}

// ---------------- small utility kernels --------------------------------------
__global__ void zero_counts_kernel() {
    if (threadIdx.x < NE) g_ecnt[threadIdx.x] = 0;
}

__global__ void rmsnorm_kernel(const float* __restrict__ x,
                               const float* __restrict__ w,
                               float* __restrict__ out) {
    int row = blockIdx.x;
    const float* xr = x + (size_t)row * DIM;
    float ss = 0.f;
    for (int i = threadIdx.x; i < DIM; i += 256) { float v = xr[i]; ss += v * v; }
    __shared__ float red[256];
    red[threadIdx.x] = ss; __syncthreads();
    for (int st = 128; st > 0; st >>= 1) {
        if (threadIdx.x < st) red[threadIdx.x] += red[threadIdx.x + st];
        __syncthreads();
    }
    float rstd = rsqrtf(red[0] / (float)DIM + EPS);
    for (int i = threadIdx.x; i < DIM; i += 256)
        out[(size_t)row * DIM + i] = xr[i] * rstd * w[i];
}

__global__ void qknorm_rope_kernel(const float* __restrict__ qnw,
                                   const float* __restrict__ knw,
                                   const float* __restrict__ cosp,
                                   const float* __restrict__ sinp)
{
    int s = blockIdx.x, h2 = blockIdx.y, d = threadIdx.x;   // 128 threads
    float* ptr; const float* w;
    if (h2 < H) { ptr = g_qt + (size_t)h2       * S * HD + (size_t)s * HD; w = qnw; }
    else        { ptr = g_kt + (size_t)(h2 - H) * S * HD + (size_t)s * HD; w = knw; }
    __shared__ float row[HD];
    __shared__ float red[HD];
    float v = ptr[d];
    red[d] = v * v; __syncthreads();
    for (int st = 64; st > 0; st >>= 1) {
        if (d < st) red[d] += red[d + st];
        __syncthreads();
    }
    float rstd = rsqrtf(red[0] / (float)HD + EPS);
    row[d] = v * rstd * w[d];
    __syncthreads();
    float rot = (d < 64) ? -row[d + 64] : row[d - 64];
    ptr[d] = row[d] * cosp[s * HD + d] + rot * sinp[s * HD + d];
}

__global__ void softmax_kernel()
{
    int s = blockIdx.x, h = blockIdx.y, tid = threadIdx.x;   // 128 threads
    float* row = g_scores + (size_t)h * S * S + (size_t)s * S;
    int nk = s + 1;
    __shared__ float red[128];
    float m = -1e30f;
    for (int i = tid; i < nk; i += 128) m = fmaxf(m, row[i]);
    red[tid] = m; __syncthreads();
    for (int st = 64; st > 0; st >>= 1) {
        if (tid < st) red[tid] = fmaxf(red[tid], red[tid + st]);
        __syncthreads();
    }
    m = red[0]; __syncthreads();
    float sum = 0.f;
    for (int i = tid; i < nk; i += 128) {
        float e = expf(row[i] - m);
        row[i] = e; sum += e;
    }
    red[tid] = sum; __syncthreads();
    for (int st = 64; st > 0; st >>= 1) {
        if (tid < st) red[tid] += red[tid + st];
        __syncthreads();
    }
    float inv = 1.f / red[0];
    for (int i = tid; i < nk; i += 128) row[i] *= inv;
    for (int i = nk + tid; i < S; i += 128) row[i] = 0.f;
}

__global__ void router_kernel(const float* __restrict__ rw)
{
    int t = blockIdx.x, tid = threadIdx.x;   // 128 threads
    __shared__ float hrow[DIM];
    __shared__ float logits[NE];
    for (int i = tid; i < DIM; i += 128) hrow[i] = g_hn[(size_t)t * DIM + i];
    __syncthreads();
    if (tid < NE) {
        const float* r = rw + (size_t)tid * DIM;
        float acc = 0.f;
        for (int i = 0; i < DIM; i++) acc += hrow[i] * r[i];
        logits[tid] = acc;
    }
    __syncthreads();
    if (tid == 0) {
        float m = -1e30f;
        for (int e = 0; e < NE; e++) m = fmaxf(m, logits[e]);
        float pr[NE]; float sum = 0.f;
        for (int e = 0; e < NE; e++) { pr[e] = expf(logits[e] - m); sum += pr[e]; }
        float invs = 1.f / sum;
        for (int e = 0; e < NE; e++) pr[e] *= invs;
        int   ti[TOPK]; float tw[TOPK]; float wsum = 0.f;
        for (int kk = 0; kk < TOPK; kk++) {
            int best = 0; float bv = -1.f;
            for (int e = 0; e < NE; e++) if (pr[e] > bv) { bv = pr[e]; best = e; }
            ti[kk] = best; tw[kk] = bv; pr[best] = -2.f; wsum += bv;
        }
        float inv = 1.f / (wsum + 1e-20f);
        for (int kk = 0; kk < TOPK; kk++) {
            int e = ti[kk];
            int pos = atomicAdd(&g_ecnt[e], 1);
            g_etok[e * S + pos] = t;
            g_ew  [e * S + pos] = tw[kk] * inv;
        }
    }
}

__global__ void silu_kernel()
{
    int slot = blockIdx.x, e = blockIdx.y;
    if (slot >= g_ecnt[e]) return;
    size_t base = (size_t)(e * S + slot) * FF;
    for (int i = threadIdx.x; i < FF; i += 256) {
        float g = g_midg[base + i], u = g_midu[base + i];
        g_midg[base + i] = g / (1.f + expf(-g)) * u;
    }
}

// ================== HMMA GEMM kernels =========================================

// QKV: grid (40, 8). x<32: q head; [32,36): k head; [36,40): v head (-> V^T).
__global__ __launch_bounds__(256) void qkv_kernel(
    const float* __restrict__ xn, const float* __restrict__ wq,
    const float* __restrict__ wk, const float* __restrict__ wv)
{
    __shared__ SmemT sm;
    int nt = blockIdx.x, mBase = blockIdx.y * 64;
    const float* B; int head, fam;
    if (nt < H)           { B = wq; head = nt;          fam = 0; }
    else if (nt < H + HK) { B = wk; head = nt - H;      fam = 1; }
    else                  { B = wv; head = nt - H - HK; fam = 2; }
    float acc[8][4] = {};
    mma_gemm(sm, xn, DIM, nullptr, mBase, B, DIM, head * HD, DIM, acc);
    int lane = threadIdx.x & 31, wid = threadIdx.x >> 5;
    int wm = wid >> 2, wn = wid & 3;
    #pragma unroll
    for (int mt = 0; mt < 2; mt++)
        #pragma unroll
        for (int ntl = 0; ntl < 4; ntl++) {
            int r0  = mBase + wm*32 + mt*16 + (lane>>2);
            int col = wn*32 + ntl*8 + (lane&3)*2;
            float* a = acc[mt*4+ntl];
            if (fam == 0) {
                float* o = g_qt + (size_t)head*S*HD;
                *(float2*)&o[(size_t)r0*HD + col]     = make_float2(a[0], a[1]);
                *(float2*)&o[(size_t)(r0+8)*HD + col] = make_float2(a[2], a[3]);
            } else if (fam == 1) {
                float* o = g_kt + (size_t)head*S*HD;
                *(float2*)&o[(size_t)r0*HD + col]     = make_float2(a[0], a[1]);
                *(float2*)&o[(size_t)(r0+8)*HD + col] = make_float2(a[2], a[3]);
            } else {
                float* o = g_vtT + (size_t)head*HD*S;
                o[(size_t)col*S     + r0]     = a[0];
                o[(size_t)(col+1)*S + r0]     = a[1];
                o[(size_t)col*S     + r0 + 8] = a[2];
                o[(size_t)(col+1)*S + r0 + 8] = a[3];
            }
        }
}

// scores: grid (4, 8, 32). Skip fully-masked tiles.
__global__ __launch_bounds__(256) void scores_kernel()
{
    int h = blockIdx.z, mBase = blockIdx.y * 64, nBase = blockIdx.x * 128;
    if (nBase > mBase + 63) return;
    __shared__ SmemT sm;
    int kvh = h / GRP;
    float acc[8][4] = {};
    mma_gemm(sm, g_qt + (size_t)h * S * HD, HD, nullptr, mBase,
             g_kt + (size_t)kvh * S * HD, HD, nBase, HD, acc);
    const float alpha = 0.08838834764831845f;   // 1/sqrt(128)
    float* C = g_scores + (size_t)h * S * S;
    int lane = threadIdx.x & 31, wid = threadIdx.x >> 5;
    int wm = wid >> 2, wn = wid & 3;
    #pragma unroll
    for (int mt = 0; mt < 2; mt++)
        #pragma unroll
        for (int ntl = 0; ntl < 4; ntl++) {
            int r0  = mBase + wm*32 + mt*16 + (lane>>2);
            int col = nBase + wn*32 + ntl*8 + (lane&3)*2;
            float* a = acc[mt*4+ntl];
            *(float2*)&C[(size_t)r0*S + col]     = make_float2(a[0]*alpha, a[1]*alpha);
            *(float2*)&C[(size_t)(r0+8)*S + col] = make_float2(a[2]*alpha, a[3]*alpha);
        }
}

// pv: grid (1, 8, 32). A = softmaxed scores, B = V^T.
__global__ __launch_bounds__(256) void pv_kernel()
{
    __shared__ SmemT sm;
    int h = blockIdx.z, mBase = blockIdx.y * 64;
    int kvh = h / GRP;
    float acc[8][4] = {};
    mma_gemm(sm, g_scores + (size_t)h * S * S, S, nullptr, mBase,
             g_vtT + (size_t)kvh * HD * S, S, 0, S, acc);
    int lane = threadIdx.x & 31, wid = threadIdx.x >> 5;
    int wm = wid >> 2, wn = wid & 3;
    #pragma unroll
    for (int mt = 0; mt < 2; mt++)
        #pragma unroll
        for (int ntl = 0; ntl < 4; ntl++) {
            int r0  = mBase + wm*32 + mt*16 + (lane>>2);
            int col = h*HD + wn*32 + ntl*8 + (lane&3)*2;
            float* a = acc[mt*4+ntl];
            *(float2*)&g_attn[(size_t)r0*NQK + col]     = make_float2(a[0], a[1]);
            *(float2*)&g_attn[(size_t)(r0+8)*NQK + col] = make_float2(a[2], a[3]);
        }
}

// wo: grid (16, 8). out = attn @ wo^T + x  -> d_out
__global__ __launch_bounds__(256) void wo_kernel(
    const float* __restrict__ wo_w, const float* __restrict__ x,
    float* __restrict__ out)
{
    __shared__ SmemT sm;
    int nBase = blockIdx.x * 128, mBase = blockIdx.y * 64;
    float acc[8][4] = {};
    mma_gemm(sm, g_attn, NQK, nullptr, mBase, wo_w, NQK, nBase, NQK, acc);
    int lane = threadIdx.x & 31, wid = threadIdx.x >> 5;
    int wm = wid >> 2, wn = wid & 3;
    #pragma unroll
    for (int mt = 0; mt < 2; mt++)
        #pragma unroll
        for (int ntl = 0; ntl < 4; ntl++) {
            int r0  = mBase + wm*32 + mt*16 + (lane>>2);
            int col = nBase + wn*32 + ntl*8 + (lane&3)*2;
            float* a = acc[mt*4+ntl];
            size_t i0 = (size_t)r0*DIM + col, i1 = (size_t)(r0+8)*DIM + col;
            float2 x0 = *(const float2*)&x[i0], x1 = *(const float2*)&x[i1];
            *(float2*)&out[i0] = make_float2(a[0] + x0.x, a[1] + x0.y);
            *(float2*)&out[i1] = make_float2(a[2] + x1.x, a[3] + x1.y);
        }
}

// moe mid: grid (12, 8, 64). x<6 gate, else up. Gathered A rows.
__global__ __launch_bounds__(256) void moe_mid_kernel(
    const float* __restrict__ gate_w, const float* __restrict__ up_w)
{
    int e = blockIdx.z;
    int Me = g_ecnt[e];
    int rowBase = blockIdx.y * 64;
    if (rowBase >= Me) return;
    __shared__ SmemT sm;
    __shared__ int tok[64];
    if (threadIdx.x < 64)
        tok[threadIdx.x] = g_etok[e * S + min(rowBase + (int)threadIdx.x, Me - 1)];
    __syncthreads();
    int xt = blockIdx.x;
    const float* B; float* C; int nBase;
    if (xt < 6) { B = gate_w + (size_t)e * FF * DIM; nBase = xt * 128;       C = g_midg; }
    else        { B = up_w   + (size_t)e * FF * DIM; nBase = (xt - 6) * 128; C = g_midu; }
    float acc[8][4] = {};
    mma_gemm(sm, g_hn, DIM, tok, 0, B, DIM, nBase, DIM, acc);
    int lane = threadIdx.x & 31, wid = threadIdx.x >> 5;
    int wm = wid >> 2, wn = wid & 3;
    #pragma unroll
    for (int mt = 0; mt < 2; mt++)
        #pragma unroll
        for (int ntl = 0; ntl < 4; ntl++) {
            int lr  = wm*32 + mt*16 + (lane>>2);
            int col = nBase + wn*32 + ntl*8 + (lane&3)*2;
            float* a = acc[mt*4+ntl];
            int s0 = rowBase + lr, s1 = s0 + 8;
            if (s0 < Me)
                *(float2*)&C[(size_t)(e*S + s0)*FF + col] = make_float2(a[0], a[1]);
            if (s1 < Me)
                *(float2*)&C[(size_t)(e*S + s1)*FF + col] = make_float2(a[2], a[3]);
        }
}

// moe down: grid (16, 8, 64). Weighted atomic scatter onto out.
__global__ __launch_bounds__(256) void moe_down_kernel(
    const float* __restrict__ down_w, float* __restrict__ out)
{
    int e = blockIdx.z;
    int Me = g_ecnt[e];
    int rowBase = blockIdx.y * 64;
    if (rowBase >= Me) return;
    __shared__ SmemT sm;
    __shared__ int tok[64];
    __shared__ float wts[64];
    if (threadIdx.x < 64) {
        int sl = min(rowBase + (int)threadIdx.x, Me - 1);
        tok[threadIdx.x] = g_etok[e * S + sl];
        wts[threadIdx.x] = g_ew  [e * S + sl];
    }
    __syncthreads();
    int nBase = blockIdx.x * 128;
    float acc[8][4] = {};
    mma_gemm(sm, g_midg + (size_t)e * S * FF, FF, nullptr, rowBase,
             down_w + (size_t)e * DIM * FF, FF, nBase, FF, acc);
    int lane = threadIdx.x & 31, wid = threadIdx.x >> 5;
    int wm = wid >> 2, wn = wid & 3;
    #pragma unroll
    for (int mt = 0; mt < 2; mt++)
        #pragma unroll
        for (int ntl = 0; ntl < 4; ntl++) {
            int lr  = wm*32 + mt*16 + (lane>>2);
            int col = nBase + wn*32 + ntl*8 + (lane&3)*2;
            float* a = acc[mt*4+ntl];
            int s0 = rowBase + lr, s1 = s0 + 8;
            if (s0 < Me) {
                int t = tok[lr]; float w = wts[lr];
                atomicAdd(&out[(size_t)t*DIM + col],     a[0]*w);
                atomicAdd(&out[(size_t)t*DIM + col + 1], a[1]*w);
            }
            if (s1 < Me) {
                int t = tok[lr+8]; float w = wts[lr+8];
                atomicAdd(&out[(size_t)t*DIM + col],     a[2]*w);
                atomicAdd(&out[(size_t)t*DIM + col + 1], a[3]*w);
            }
        }
}

// ---------------- launch ------------------------------------------------------
extern "C" void kernel_launch(void* const* d_in, const int* in_sizes, int n_in,
                              void* d_out, int out_size)
{
    const float* x    = (const float*)d_in[0];
    const float* cosp = (const float*)d_in[1];
    const float* sinp = (const float*)d_in[2];
    const float* n1w  = (const float*)d_in[3];
    const float* wq   = (const float*)d_in[4];
    const float* wk   = (const float*)d_in[5];
    const float* wv   = (const float*)d_in[6];
    const float* wo_w = (const float*)d_in[7];
    const float* qnw  = (const float*)d_in[8];
    const float* knw  = (const float*)d_in[9];
    const float* n2w  = (const float*)d_in[10];
    const float* rw   = (const float*)d_in[11];
    const float* gw   = (const float*)d_in[12];
    const float* uw   = (const float*)d_in[13];
    const float* dw   = (const float*)d_in[14];
    float* out = (float*)d_out;

    float *xn, *hn;
    cudaGetSymbolAddress((void**)&xn, g_xn);
    cudaGetSymbolAddress((void**)&hn, g_hn);

    zero_counts_kernel<<<1, 64>>>();
    rmsnorm_kernel<<<S, 256>>>(x, n1w, xn);
    qkv_kernel<<<dim3(H + 2*HK, S/64), 256>>>(xn, wq, wk, wv);
    qknorm_rope_kernel<<<dim3(S, H + HK), HD>>>(qnw, knw, cosp, sinp);
    scores_kernel<<<dim3(S/128, S/64, H), 256>>>();
    softmax_kernel<<<dim3(S, H), 128>>>();
    pv_kernel<<<dim3(1, S/64, H), 256>>>();
    wo_kernel<<<dim3(DIM/128, S/64), 256>>>(wo_w, x, out);
    rmsnorm_kernel<<<S, 256>>>(out, n2w, hn);
    router_kernel<<<S, 128>>>(rw);
    moe_mid_kernel<<<dim3(12, S/64, NE), 256>>>(gw, uw);
    silu_kernel<<<dim3(S, NE), 256>>>();
    moe_down_kernel<<<dim3(DIM/128, S/64, NE), 256>>>(dw, out);
}

// round 11
// speedup vs baseline: 1.9117x; 1.0180x over previous
#include <cuda_runtime.h>
#include <cuda_bf16.h>
#include <math.h>
#include <stdint.h>

#define S    512
#define DIM  2048
#define H    32
#define HK   4
#define HD   128
#define NQK  (H*HD)    // 4096
#define NKV  (HK*HD)   // 512
#define NE   64
#define TOPK 8
#define FF   768
#define EPS  1e-6f
#define GRP  (H/HK)    // 8

// GEMM tile config: BM=64, BN=128, BK=32, 256 threads (8 warps, warp tile 32x32)
#define AW 20   // smem words per row (16 data + 4 pad) -> conflict-free frag LDS

// ---------------- scratch (static device globals; no allocation) -------------
__device__ float g_xn[S*DIM];
__device__ float g_qt[(size_t)H*S*HD];      // [h][s][d]
__device__ float g_kt[(size_t)HK*S*HD];     // [h][s][d]
__device__ float g_vtT[(size_t)HK*HD*S];    // [h][d][s]  (transposed for PV)
__device__ float g_scores[(size_t)H*S*S];
__device__ float g_attn[S*NQK];             // [s][h*HD+d]
__device__ float g_hn[S*DIM];
__device__ float g_midg[(size_t)NE*S*FF];
__device__ float g_midu[(size_t)NE*S*FF];
__device__ int   g_ecnt[NE];
__device__ int   g_etok[NE*S];
__device__ float g_ew  [NE*S];

// ---------------- helpers ----------------------------------------------------
struct SmemT {
    uint32_t Ahi[64*AW];
    uint32_t Alo[64*AW];
    uint32_t Bhi[128*AW];
    uint32_t Blo[128*AW];
};  // 30720 bytes
#define DSMEM_BYTES (2 * (int)sizeof(SmemT))   // 61440, double-buffered

__device__ __forceinline__ uint32_t s2u(const void* p) {
    uint32_t a;
    asm("{ .reg .u64 t; cvta.to.shared.u64 t, %1; cvt.u32.u64 %0, t; }"
        : "=r"(a) : "l"(p));
    return a;
}

__device__ __forceinline__ void ldsm4(uint32_t* r, uint32_t addr) {
    asm volatile("ldmatrix.sync.aligned.m8n8.x4.shared.b16 {%0,%1,%2,%3}, [%4];"
                 : "=r"(r[0]), "=r"(r[1]), "=r"(r[2]), "=r"(r[3]) : "r"(addr));
}

__device__ __forceinline__ void mma16816(float* c, const uint32_t* a, const uint32_t* b) {
    asm volatile(
        "mma.sync.aligned.m16n8k16.row.col.f32.bf16.bf16.f32 "
        "{%0,%1,%2,%3}, {%4,%5,%6,%7}, {%8,%9}, {%0,%1,%2,%3};"
        : "+f"(c[0]), "+f"(c[1]), "+f"(c[2]), "+f"(c[3])
        : "r"(a[0]), "r"(a[1]), "r"(a[2]), "r"(a[3]), "r"(b[0]), "r"(b[1]));
}

__device__ __forceinline__ void pack_hl(float a, float b, uint32_t& hi, uint32_t& lo) {
    __nv_bfloat162 h = __floats2bfloat162_rn(a, b);
    float ah = __bfloat162float(h.x), bh = __bfloat162float(h.y);
    __nv_bfloat162 l = __floats2bfloat162_rn(a - ah, b - bh);
    hi = *reinterpret_cast<uint32_t*>(&h);
    lo = *reinterpret_cast<uint32_t*>(&l);
}

__device__ __forceinline__ void cvt_store(SmemT& s, int awBase, int bwBase,
                                          const float4* va, const float4* vb) {
    #pragma unroll
    for (int j = 0; j < 2; j++) {
        uint32_t h0, l0, h1, l1;
        pack_hl(va[j].x, va[j].y, h0, l0);
        pack_hl(va[j].z, va[j].w, h1, l1);
        *(uint2*)&s.Ahi[awBase + j*2] = make_uint2(h0, h1);
        *(uint2*)&s.Alo[awBase + j*2] = make_uint2(l0, l1);
    }
    #pragma unroll
    for (int j = 0; j < 4; j++) {
        uint32_t h0, l0, h1, l1;
        pack_hl(vb[j].x, vb[j].y, h0, l0);
        pack_hl(vb[j].z, vb[j].w, h1, l1);
        *(uint2*)&s.Bhi[bwBase + j*2] = make_uint2(h0, h1);
        *(uint2*)&s.Blo[bwBase + j*2] = make_uint2(l0, l1);
    }
}

// fragment loads via ldmatrix; mappings verified against the scalar-load layout
__device__ __forceinline__ void mma_step(uint32_t aHiB, uint32_t aLoB,
                                         uint32_t bHiB, uint32_t bLoB,
                                         int ks, int wm, int wn, int lane,
                                         float (&acc)[8][4]) {
    const int kw = ks * 8;
    const int r = lane & 7, sub = lane >> 3;
    uint32_t ah[2][4], al[2][4], bh[2][4], bl[2][4];
    #pragma unroll
    for (int mt = 0; mt < 2; mt++) {
        uint32_t off = (uint32_t)(((wm*32 + mt*16 + r + (sub&1)*8) * AW
                                   + kw + (sub>>1)*4) * 4);
        ldsm4(ah[mt], aHiB + off);
        ldsm4(al[mt], aLoB + off);
    }
    #pragma unroll
    for (int p = 0; p < 2; p++) {
        uint32_t off = (uint32_t)(((wn*32 + p*16 + r + (sub>>1)*8) * AW
                                   + kw + (sub&1)*4) * 4);
        ldsm4(bh[p], bHiB + off);
        ldsm4(bl[p], bLoB + off);
    }
    #pragma unroll
    for (int mt = 0; mt < 2; mt++)
        #pragma unroll
        for (int nt = 0; nt < 4; nt++) {
            uint32_t bh2[2] = { bh[nt>>1][(nt&1)*2], bh[nt>>1][(nt&1)*2+1] };
            uint32_t bl2[2] = { bl[nt>>1][(nt&1)*2], bl[nt>>1][(nt&1)*2+1] };
            mma16816(acc[mt*4+nt], ah[mt], bh2);
            mma16816(acc[mt*4+nt], ah[mt], bl2);
            mma16816(acc[mt*4+nt], al[mt], bh2);
        }
}

// =============================================================================
// Core: C[64,128] = A[64,K] @ B[128 rows,K]^T, bf16 hi/lo split (3 passes),
// fp32 accum in registers. DOUBLE-buffered smem, ONE sync per 32-chunk:
//   consume buf[t&1] (mma) -> produce buf[(t+1)&1] (cvt) -> LDG t+2 -> bar.
// rowTok (smem, 64 ints) gathers A rows if non-null. K % 32 == 0.
// =============================================================================
__device__ __forceinline__ void mma_gemm(
    char* smraw,
    const float* __restrict__ A, int lda, const int* rowTok, int mBase,
    const float* __restrict__ B, int ldb, int nBase, int K,
    float (&acc)[8][4])
{
    const int tid  = threadIdx.x;
    const int lane = tid & 31, wid = tid >> 5;
    const int wm = wid >> 2, wn = wid & 3;

    const int rA = tid >> 2, qA = tid & 3;          // A: 64 rows x 8 floats
    const int rB = tid >> 1, hB = tid & 1;          // B: 128 rows x 16 floats
    const int rowA = rowTok ? rowTok[rA] : (mBase + rA);
    const float* Ap = A + (size_t)rowA * lda + qA * 8;
    const float* Bp = B + (size_t)(nBase + rB) * ldb + hB * 16;

    const int nch = K >> 5;
    const int awBase = rA * AW + qA * 4;
    const int bwBase = rB * AW + hB * 8;

    SmemT* buf0 = (SmemT*)smraw;
    SmemT* buf1 = (SmemT*)(smraw + sizeof(SmemT));
    const uint32_t b0 = s2u(buf0);

    float4 va[2], vb[4];
    va[0] = *(const float4*)(Ap);
    va[1] = *(const float4*)(Ap + 4);
    #pragma unroll
    for (int j = 0; j < 4; j++) vb[j] = *(const float4*)(Bp + j * 4);
    cvt_store(*buf0, awBase, bwBase, va, vb);
    if (nch > 1) {
        va[0] = *(const float4*)(Ap + 32);
        va[1] = *(const float4*)(Ap + 36);
        #pragma unroll
        for (int j = 0; j < 4; j++) vb[j] = *(const float4*)(Bp + 32 + j * 4);
    }
    __syncthreads();

    for (int t = 0; t < nch; t++) {
        const uint32_t co = b0 + (uint32_t)((t & 1) * (int)sizeof(SmemT));
        const uint32_t aHiB = co, aLoB = co + 5120;
        const uint32_t bHiB = co + 10240, bLoB = co + 20480;
        mma_step(aHiB, aLoB, bHiB, bLoB, 0, wm, wn, lane, acc);
        mma_step(aHiB, aLoB, bHiB, bLoB, 1, wm, wn, lane, acc);
        if (t + 1 < nch) {
            SmemT& nxt = ((t + 1) & 1) ? *buf1 : *buf0;
            cvt_store(nxt, awBase, bwBase, va, vb);
            if (t + 2 < nch) {
                va[0] = *(const float4*)(Ap + (t+2)*32);
                va[1] = *(const float4*)(Ap + (t+2)*32 + 4);
                #pragma unroll
                for (int j = 0; j < 4; j++)
                    vb[j] = *(const float4*)(Bp + (t+2)*32 + j*4);
            }
        }
        __syncthreads();
    }
}

// ---------------- small utility kernels --------------------------------------
__global__ void zero_counts_kernel() {
    if (threadIdx.x < NE) g_ecnt[threadIdx.x] = 0;
}

__global__ void rmsnorm_kernel(const float* __restrict__ x,
                               const float* __restrict__ w,
                               float* __restrict__ out) {
    int row = blockIdx.x;
    const float* xr = x + (size_t)row * DIM;
    float ss = 0.f;
    for (int i = threadIdx.x; i < DIM; i += 256) { float v = xr[i]; ss += v * v; }
    __shared__ float red[256];
    red[threadIdx.x] = ss; __syncthreads();
    for (int st = 128; st > 0; st >>= 1) {
        if (threadIdx.x < st) red[threadIdx.x] += red[threadIdx.x + st];
        __syncthreads();
    }
    float rstd = rsqrtf(red[0] / (float)DIM + EPS);
    for (int i = threadIdx.x; i < DIM; i += 256)
        out[(size_t)row * DIM + i] = xr[i] * rstd * w[i];
}

__global__ void qknorm_rope_kernel(const float* __restrict__ qnw,
                                   const float* __restrict__ knw,
                                   const float* __restrict__ cosp,
                                   const float* __restrict__ sinp)
{
    int s = blockIdx.x, h2 = blockIdx.y, d = threadIdx.x;   // 128 threads
    float* ptr; const float* w;
    if (h2 < H) { ptr = g_qt + (size_t)h2       * S * HD + (size_t)s * HD; w = qnw; }
    else        { ptr = g_kt + (size_t)(h2 - H) * S * HD + (size_t)s * HD; w = knw; }
    __shared__ float row[HD];
    __shared__ float red[HD];
    float v = ptr[d];
    red[d] = v * v; __syncthreads();
    for (int st = 64; st > 0; st >>= 1) {
        if (d < st) red[d] += red[d + st];
        __syncthreads();
    }
    float rstd = rsqrtf(red[0] / (float)HD + EPS);
    row[d] = v * rstd * w[d];
    __syncthreads();
    float rot = (d < 64) ? -row[d + 64] : row[d - 64];
    ptr[d] = row[d] * cosp[s * HD + d] + rot * sinp[s * HD + d];
}

__global__ void softmax_kernel()
{
    int s = blockIdx.x, h = blockIdx.y, tid = threadIdx.x;   // 128 threads
    float* row = g_scores + (size_t)h * S * S + (size_t)s * S;
    int nk = s + 1;
    __shared__ float red[128];
    float m = -1e30f;
    for (int i = tid; i < nk; i += 128) m = fmaxf(m, row[i]);
    red[tid] = m; __syncthreads();
    for (int st = 64; st > 0; st >>= 1) {
        if (tid < st) red[tid] = fmaxf(red[tid], red[tid + st]);
        __syncthreads();
    }
    m = red[0]; __syncthreads();
    float sum = 0.f;
    for (int i = tid; i < nk; i += 128) {
        float e = expf(row[i] - m);
        row[i] = e; sum += e;
    }
    red[tid] = sum; __syncthreads();
    for (int st = 64; st > 0; st >>= 1) {
        if (tid < st) red[tid] += red[tid + st];
        __syncthreads();
    }
    float inv = 1.f / red[0];
    for (int i = tid; i < nk; i += 128) row[i] *= inv;
    for (int i = nk + tid; i < S; i += 128) row[i] = 0.f;
}

__global__ void router_kernel(const float* __restrict__ rw)
{
    int t = blockIdx.x, tid = threadIdx.x;   // 128 threads
    __shared__ float hrow[DIM];
    __shared__ float logits[NE];
    for (int i = tid; i < DIM; i += 128) hrow[i] = g_hn[(size_t)t * DIM + i];
    __syncthreads();
    if (tid < NE) {
        const float* r = rw + (size_t)tid * DIM;
        float acc = 0.f;
        for (int i = 0; i < DIM; i++) acc += hrow[i] * r[i];
        logits[tid] = acc;
    }
    __syncthreads();
    if (tid == 0) {
        float m = -1e30f;
        for (int e = 0; e < NE; e++) m = fmaxf(m, logits[e]);
        float pr[NE]; float sum = 0.f;
        for (int e = 0; e < NE; e++) { pr[e] = expf(logits[e] - m); sum += pr[e]; }
        float invs = 1.f / sum;
        for (int e = 0; e < NE; e++) pr[e] *= invs;
        int   ti[TOPK]; float tw[TOPK]; float wsum = 0.f;
        for (int kk = 0; kk < TOPK; kk++) {
            int best = 0; float bv = -1.f;
            for (int e = 0; e < NE; e++) if (pr[e] > bv) { bv = pr[e]; best = e; }
            ti[kk] = best; tw[kk] = bv; pr[best] = -2.f; wsum += bv;
        }
        float inv = 1.f / (wsum + 1e-20f);
        for (int kk = 0; kk < TOPK; kk++) {
            int e = ti[kk];
            int pos = atomicAdd(&g_ecnt[e], 1);
            g_etok[e * S + pos] = t;
            g_ew  [e * S + pos] = tw[kk] * inv;
        }
    }
}

__global__ void silu_kernel()
{
    int slot = blockIdx.x, e = blockIdx.y;
    if (slot >= g_ecnt[e]) return;
    size_t base = (size_t)(e * S + slot) * FF;
    for (int i = threadIdx.x; i < FF; i += 256) {
        float g = g_midg[base + i], u = g_midu[base + i];
        g_midg[base + i] = g / (1.f + expf(-g)) * u;
    }
}

// ================== HMMA GEMM kernels =========================================

// QKV: grid (40, 8). x<32: q head; [32,36): k head; [36,40): v head (-> V^T).
__global__ __launch_bounds__(256) void qkv_kernel(
    const float* __restrict__ xn, const float* __restrict__ wq,
    const float* __restrict__ wk, const float* __restrict__ wv)
{
    extern __shared__ char smraw[];
    int nt = blockIdx.x, mBase = blockIdx.y * 64;
    const float* B; int head, fam;
    if (nt < H)           { B = wq; head = nt;          fam = 0; }
    else if (nt < H + HK) { B = wk; head = nt - H;      fam = 1; }
    else                  { B = wv; head = nt - H - HK; fam = 2; }
    float acc[8][4] = {};
    mma_gemm(smraw, xn, DIM, nullptr, mBase, B, DIM, head * HD, DIM, acc);
    int lane = threadIdx.x & 31, wid = threadIdx.x >> 5;
    int wm = wid >> 2, wn = wid & 3;
    #pragma unroll
    for (int mt = 0; mt < 2; mt++)
        #pragma unroll
        for (int ntl = 0; ntl < 4; ntl++) {
            int r0  = mBase + wm*32 + mt*16 + (lane>>2);
            int col = wn*32 + ntl*8 + (lane&3)*2;
            float* a = acc[mt*4+ntl];
            if (fam == 0) {
                float* o = g_qt + (size_t)head*S*HD;
                *(float2*)&o[(size_t)r0*HD + col]     = make_float2(a[0], a[1]);
                *(float2*)&o[(size_t)(r0+8)*HD + col] = make_float2(a[2], a[3]);
            } else if (fam == 1) {
                float* o = g_kt + (size_t)head*S*HD;
                *(float2*)&o[(size_t)r0*HD + col]     = make_float2(a[0], a[1]);
                *(float2*)&o[(size_t)(r0+8)*HD + col] = make_float2(a[2], a[3]);
            } else {
                float* o = g_vtT + (size_t)head*HD*S;
                o[(size_t)col*S     + r0]     = a[0];
                o[(size_t)(col+1)*S + r0]     = a[1];
                o[(size_t)col*S     + r0 + 8] = a[2];
                o[(size_t)(col+1)*S + r0 + 8] = a[3];
            }
        }
}

// scores: grid (4, 8, 32). Skip fully-masked tiles.
__global__ __launch_bounds__(256) void scores_kernel()
{
    int h = blockIdx.z, mBase = blockIdx.y * 64, nBase = blockIdx.x * 128;
    if (nBase > mBase + 63) return;
    extern __shared__ char smraw[];
    int kvh = h / GRP;
    float acc[8][4] = {};
    mma_gemm(smraw, g_qt + (size_t)h * S * HD, HD, nullptr, mBase,
             g_kt + (size_t)kvh * S * HD, HD, nBase, HD, acc);
    const float alpha = 0.08838834764831845f;   // 1/sqrt(128)
    float* C = g_scores + (size_t)h * S * S;
    int lane = threadIdx.x & 31, wid = threadIdx.x >> 5;
    int wm = wid >> 2, wn = wid & 3;
    #pragma unroll
    for (int mt = 0; mt < 2; mt++)
        #pragma unroll
        for (int ntl = 0; ntl < 4; ntl++) {
            int r0  = mBase + wm*32 + mt*16 + (lane>>2);
            int col = nBase + wn*32 + ntl*8 + (lane&3)*2;
            float* a = acc[mt*4+ntl];
            *(float2*)&C[(size_t)r0*S + col]     = make_float2(a[0]*alpha, a[1]*alpha);
            *(float2*)&C[(size_t)(r0+8)*S + col] = make_float2(a[2]*alpha, a[3]*alpha);
        }
}

// pv: grid (1, 8, 32). A = softmaxed scores, B = V^T.
__global__ __launch_bounds__(256) void pv_kernel()
{
    extern __shared__ char smraw[];
    int h = blockIdx.z, mBase = blockIdx.y * 64;
    int kvh = h / GRP;
    float acc[8][4] = {};
    mma_gemm(smraw, g_scores + (size_t)h * S * S, S, nullptr, mBase,
             g_vtT + (size_t)kvh * HD * S, S, 0, S, acc);
    int lane = threadIdx.x & 31, wid = threadIdx.x >> 5;
    int wm = wid >> 2, wn = wid & 3;
    #pragma unroll
    for (int mt = 0; mt < 2; mt++)
        #pragma unroll
        for (int ntl = 0; ntl < 4; ntl++) {
            int r0  = mBase + wm*32 + mt*16 + (lane>>2);
            int col = h*HD + wn*32 + ntl*8 + (lane&3)*2;
            float* a = acc[mt*4+ntl];
            *(float2*)&g_attn[(size_t)r0*NQK + col]     = make_float2(a[0], a[1]);
            *(float2*)&g_attn[(size_t)(r0+8)*NQK + col] = make_float2(a[2], a[3]);
        }
}

// wo: grid (16, 8). out = attn @ wo^T + x  -> d_out
__global__ __launch_bounds__(256) void wo_kernel(
    const float* __restrict__ wo_w, const float* __restrict__ x,
    float* __restrict__ out)
{
    extern __shared__ char smraw[];
    int nBase = blockIdx.x * 128, mBase = blockIdx.y * 64;
    float acc[8][4] = {};
    mma_gemm(smraw, g_attn, NQK, nullptr, mBase, wo_w, NQK, nBase, NQK, acc);
    int lane = threadIdx.x & 31, wid = threadIdx.x >> 5;
    int wm = wid >> 2, wn = wid & 3;
    #pragma unroll
    for (int mt = 0; mt < 2; mt++)
        #pragma unroll
        for (int ntl = 0; ntl < 4; ntl++) {
            int r0  = mBase + wm*32 + mt*16 + (lane>>2);
            int col = nBase + wn*32 + ntl*8 + (lane&3)*2;
            float* a = acc[mt*4+ntl];
            size_t i0 = (size_t)r0*DIM + col, i1 = (size_t)(r0+8)*DIM + col;
            float2 x0 = *(const float2*)&x[i0], x1 = *(const float2*)&x[i1];
            *(float2*)&out[i0] = make_float2(a[0] + x0.x, a[1] + x0.y);
            *(float2*)&out[i1] = make_float2(a[2] + x1.x, a[3] + x1.y);
        }
}

// moe mid: grid (12, 8, 64). x<6 gate, else up. Gathered A rows.
__global__ __launch_bounds__(256) void moe_mid_kernel(
    const float* __restrict__ gate_w, const float* __restrict__ up_w)
{
    int e = blockIdx.z;
    int Me = g_ecnt[e];
    int rowBase = blockIdx.y * 64;
    if (rowBase >= Me) return;
    extern __shared__ char smraw[];
    __shared__ int tok[64];
    if (threadIdx.x < 64)
        tok[threadIdx.x] = g_etok[e * S + min(rowBase + (int)threadIdx.x, Me - 1)];
    __syncthreads();
    int xt = blockIdx.x;
    const float* B; float* C; int nBase;
    if (xt < 6) { B = gate_w + (size_t)e * FF * DIM; nBase = xt * 128;       C = g_midg; }
    else        { B = up_w   + (size_t)e * FF * DIM; nBase = (xt - 6) * 128; C = g_midu; }
    float acc[8][4] = {};
    mma_gemm(smraw, g_hn, DIM, tok, 0, B, DIM, nBase, DIM, acc);
    int lane = threadIdx.x & 31, wid = threadIdx.x >> 5;
    int wm = wid >> 2, wn = wid & 3;
    #pragma unroll
    for (int mt = 0; mt < 2; mt++)
        #pragma unroll
        for (int ntl = 0; ntl < 4; ntl++) {
            int lr  = wm*32 + mt*16 + (lane>>2);
            int col = nBase + wn*32 + ntl*8 + (lane&3)*2;
            float* a = acc[mt*4+ntl];
            int s0 = rowBase + lr, s1 = s0 + 8;
            if (s0 < Me)
                *(float2*)&C[(size_t)(e*S + s0)*FF + col] = make_float2(a[0], a[1]);
            if (s1 < Me)
                *(float2*)&C[(size_t)(e*S + s1)*FF + col] = make_float2(a[2], a[3]);
        }
}

// moe down: grid (16, 8, 64). Weighted atomic scatter onto out.
__global__ __launch_bounds__(256) void moe_down_kernel(
    const float* __restrict__ down_w, float* __restrict__ out)
{
    int e = blockIdx.z;
    int Me = g_ecnt[e];
    int rowBase = blockIdx.y * 64;
    if (rowBase >= Me) return;
    extern __shared__ char smraw[];
    __shared__ int tok[64];
    __shared__ float wts[64];
    if (threadIdx.x < 64) {
        int sl = min(rowBase + (int)threadIdx.x, Me - 1);
        tok[threadIdx.x] = g_etok[e * S + sl];
        wts[threadIdx.x] = g_ew  [e * S + sl];
    }
    __syncthreads();
    int nBase = blockIdx.x * 128;
    float acc[8][4] = {};
    mma_gemm(smraw, g_midg + (size_t)e * S * FF, FF, nullptr, rowBase,
             down_w + (size_t)e * DIM * FF, FF, nBase, FF, acc);
    int lane = threadIdx.x & 31, wid = threadIdx.x >> 5;
    int wm = wid >> 2, wn = wid & 3;
    #pragma unroll
    for (int mt = 0; mt < 2; mt++)
        #pragma unroll
        for (int ntl = 0; ntl < 4; ntl++) {
            int lr  = wm*32 + mt*16 + (lane>>2);
            int col = nBase + wn*32 + ntl*8 + (lane&3)*2;
            float* a = acc[mt*4+ntl];
            int s0 = rowBase + lr, s1 = s0 + 8;
            if (s0 < Me) {
                int t = tok[lr]; float w = wts[lr];
                atomicAdd(&out[(size_t)t*DIM + col],     a[0]*w);
                atomicAdd(&out[(size_t)t*DIM + col + 1], a[1]*w);
            }
            if (s1 < Me) {
                int t = tok[lr+8]; float w = wts[lr+8];
                atomicAdd(&out[(size_t)t*DIM + col],     a[2]*w);
                atomicAdd(&out[(size_t)t*DIM + col + 1], a[3]*w);
            }
        }
}

// ---------------- launch ------------------------------------------------------
extern "C" void kernel_launch(void* const* d_in, const int* in_sizes, int n_in,
                              void* d_out, int out_size)
{
    const float* x    = (const float*)d_in[0];
    const float* cosp = (const float*)d_in[1];
    const float* sinp = (const float*)d_in[2];
    const float* n1w  = (const float*)d_in[3];
    const float* wq   = (const float*)d_in[4];
    const float* wk   = (const float*)d_in[5];
    const float* wv   = (const float*)d_in[6];
    const float* wo_w = (const float*)d_in[7];
    const float* qnw  = (const float*)d_in[8];
    const float* knw  = (const float*)d_in[9];
    const float* n2w  = (const float*)d_in[10];
    const float* rw   = (const float*)d_in[11];
    const float* gw   = (const float*)d_in[12];
    const float* uw   = (const float*)d_in[13];
    const float* dw   = (const float*)d_in[14];
    float* out = (float*)d_out;

    cudaFuncSetAttribute(qkv_kernel,      cudaFuncAttributeMaxDynamicSharedMemorySize, DSMEM_BYTES);
    cudaFuncSetAttribute(scores_kernel,   cudaFuncAttributeMaxDynamicSharedMemorySize, DSMEM_BYTES);
    cudaFuncSetAttribute(pv_kernel,       cudaFuncAttributeMaxDynamicSharedMemorySize, DSMEM_BYTES);
    cudaFuncSetAttribute(wo_kernel,       cudaFuncAttributeMaxDynamicSharedMemorySize, DSMEM_BYTES);
    cudaFuncSetAttribute(moe_mid_kernel,  cudaFuncAttributeMaxDynamicSharedMemorySize, DSMEM_BYTES);
    cudaFuncSetAttribute(moe_down_kernel, cudaFuncAttributeMaxDynamicSharedMemorySize, DSMEM_BYTES);

    float *xn, *hn;
    cudaGetSymbolAddress((void**)&xn, g_xn);
    cudaGetSymbolAddress((void**)&hn, g_hn);

    zero_counts_kernel<<<1, 64>>>();
    rmsnorm_kernel<<<S, 256>>>(x, n1w, xn);
    qkv_kernel<<<dim3(H + 2*HK, S/64), 256, DSMEM_BYTES>>>(xn, wq, wk, wv);
    qknorm_rope_kernel<<<dim3(S, H + HK), HD>>>(qnw, knw, cosp, sinp);
    scores_kernel<<<dim3(S/128, S/64, H), 256, DSMEM_BYTES>>>();
    softmax_kernel<<<dim3(S, H), 128>>>();
    pv_kernel<<<dim3(1, S/64, H), 256, DSMEM_BYTES>>>();
    wo_kernel<<<dim3(DIM/128, S/64), 256, DSMEM_BYTES>>>(wo_w, x, out);
    rmsnorm_kernel<<<S, 256>>>(out, n2w, hn);
    router_kernel<<<S, 128>>>(rw);
    moe_mid_kernel<<<dim3(12, S/64, NE), 256, DSMEM_BYTES>>>(gw, uw);
    silu_kernel<<<dim3(S, NE), 256>>>();
    moe_down_kernel<<<dim3(DIM/128, S/64, NE), 256, DSMEM_BYTES>>>(dw, out);
}

// round 13
// speedup vs baseline: 2.2036x; 1.1527x over previous
#include <cuda_runtime.h>
#include <cuda_bf16.h>
#include <cuda_fp16.h>
#include <math.h>
#include <stdint.h>

#define S    512
#define DIM  2048
#define H    32
#define HK   4
#define HD   128
#define NQK  (H*HD)    // 4096
#define NKV  (HK*HD)   // 512
#define NE   64
#define TOPK 8
#define FF   768
#define EPS  1e-6f
#define GRP  (H/HK)    // 8

// GEMM tile config: BM=64, BN=128, BK=32, 256 threads (8 warps, warp tile 32x32)
#define AW 20   // smem words per row (16 data + 4 pad) -> conflict-free frag LDS

// ---------------- scratch (static device globals; no allocation) -------------
__device__ float g_xn[S*DIM];
__device__ float g_qt[(size_t)H*S*HD];      // [h][s][d]
__device__ float g_kt[(size_t)HK*S*HD];     // [h][s][d]
__device__ float g_vtT[(size_t)HK*HD*S];    // [h][d][s]  (transposed for PV)
__device__ float g_scores[(size_t)H*S*S];
__device__ float g_attn[S*NQK];             // [s][h*HD+d]
__device__ float g_hn[S*DIM];
__device__ float g_midg[(size_t)NE*S*FF];
__device__ float g_midu[(size_t)NE*S*FF];
__device__ int   g_ecnt[NE];
__device__ int   g_etok[NE*S];
__device__ float g_ew  [NE*S];

// ---------------- common helpers ---------------------------------------------
__device__ __forceinline__ uint32_t s2u(const void* p) {
    uint32_t a;
    asm("{ .reg .u64 t; cvta.to.shared.u64 t, %1; cvt.u32.u64 %0, t; }"
        : "=r"(a) : "l"(p));
    return a;
}

__device__ __forceinline__ void ldsm4(uint32_t* r, uint32_t addr) {
    asm volatile("ldmatrix.sync.aligned.m8n8.x4.shared.b16 {%0,%1,%2,%3}, [%4];"
                 : "=r"(r[0]), "=r"(r[1]), "=r"(r[2]), "=r"(r[3]) : "r"(addr));
}

__device__ __forceinline__ void mma_bf(float* c, const uint32_t* a, const uint32_t* b) {
    asm volatile(
        "mma.sync.aligned.m16n8k16.row.col.f32.bf16.bf16.f32 "
        "{%0,%1,%2,%3}, {%4,%5,%6,%7}, {%8,%9}, {%0,%1,%2,%3};"
        : "+f"(c[0]), "+f"(c[1]), "+f"(c[2]), "+f"(c[3])
        : "r"(a[0]), "r"(a[1]), "r"(a[2]), "r"(a[3]), "r"(b[0]), "r"(b[1]));
}
__device__ __forceinline__ void mma_fp(float* c, const uint32_t* a, const uint32_t* b) {
    asm volatile(
        "mma.sync.aligned.m16n8k16.row.col.f32.f16.f16.f32 "
        "{%0,%1,%2,%3}, {%4,%5,%6,%7}, {%8,%9}, {%0,%1,%2,%3};"
        : "+f"(c[0]), "+f"(c[1]), "+f"(c[2]), "+f"(c[3])
        : "r"(a[0]), "r"(a[1]), "r"(a[2]), "r"(a[3]), "r"(b[0]), "r"(b[1]));
}

// ================= TRUNK core: bf16 hi/lo 3-pass (R11, proven 4.6e-6) ========
struct SmemT3 {
    uint32_t Ahi[64*AW];
    uint32_t Alo[64*AW];
    uint32_t Bhi[128*AW];
    uint32_t Blo[128*AW];
};  // 30720 bytes
#define DSMEM3 (2 * (int)sizeof(SmemT3))   // 61440

__device__ __forceinline__ void pack_hl(float a, float b, uint32_t& hi, uint32_t& lo) {
    __nv_bfloat162 h = __floats2bfloat162_rn(a, b);
    float ah = __bfloat162float(h.x), bh = __bfloat162float(h.y);
    __nv_bfloat162 l = __floats2bfloat162_rn(a - ah, b - bh);
    hi = *reinterpret_cast<uint32_t*>(&h);
    lo = *reinterpret_cast<uint32_t*>(&l);
}

__device__ __forceinline__ void cvt_store3(SmemT3& s, int awBase, int bwBase,
                                           const float4* va, const float4* vb) {
    #pragma unroll
    for (int j = 0; j < 2; j++) {
        uint32_t h0, l0, h1, l1;
        pack_hl(va[j].x, va[j].y, h0, l0);
        pack_hl(va[j].z, va[j].w, h1, l1);
        *(uint2*)&s.Ahi[awBase + j*2] = make_uint2(h0, h1);
        *(uint2*)&s.Alo[awBase + j*2] = make_uint2(l0, l1);
    }
    #pragma unroll
    for (int j = 0; j < 4; j++) {
        uint32_t h0, l0, h1, l1;
        pack_hl(vb[j].x, vb[j].y, h0, l0);
        pack_hl(vb[j].z, vb[j].w, h1, l1);
        *(uint2*)&s.Bhi[bwBase + j*2] = make_uint2(h0, h1);
        *(uint2*)&s.Blo[bwBase + j*2] = make_uint2(l0, l1);
    }
}

__device__ __forceinline__ void mma_step3(uint32_t aHiB, uint32_t aLoB,
                                          uint32_t bHiB, uint32_t bLoB,
                                          int ks, int wm, int wn, int lane,
                                          float (&acc)[8][4]) {
    const int kw = ks * 8;
    const int r = lane & 7, sub = lane >> 3;
    uint32_t ah[2][4], al[2][4], bh[2][4], bl[2][4];
    #pragma unroll
    for (int mt = 0; mt < 2; mt++) {
        uint32_t off = (uint32_t)(((wm*32 + mt*16 + r + (sub&1)*8) * AW
                                   + kw + (sub>>1)*4) * 4);
        ldsm4(ah[mt], aHiB + off);
        ldsm4(al[mt], aLoB + off);
    }
    #pragma unroll
    for (int p = 0; p < 2; p++) {
        uint32_t off = (uint32_t)(((wn*32 + p*16 + r + (sub>>1)*8) * AW
                                   + kw + (sub&1)*4) * 4);
        ldsm4(bh[p], bHiB + off);
        ldsm4(bl[p], bLoB + off);
    }
    #pragma unroll
    for (int mt = 0; mt < 2; mt++)
        #pragma unroll
        for (int nt = 0; nt < 4; nt++) {
            uint32_t bh2[2] = { bh[nt>>1][(nt&1)*2], bh[nt>>1][(nt&1)*2+1] };
            uint32_t bl2[2] = { bl[nt>>1][(nt&1)*2], bl[nt>>1][(nt&1)*2+1] };
            mma_bf(acc[mt*4+nt], ah[mt], bh2);
            mma_bf(acc[mt*4+nt], ah[mt], bl2);
            mma_bf(acc[mt*4+nt], al[mt], bh2);
        }
}

__device__ __forceinline__ void mma_gemm3(
    char* smraw,
    const float* __restrict__ A, int lda, const int* rowTok, int mBase,
    const float* __restrict__ B, int ldb, int nBase, int K,
    float (&acc)[8][4])
{
    const int tid  = threadIdx.x;
    const int lane = tid & 31, wid = tid >> 5;
    const int wm = wid >> 2, wn = wid & 3;

    const int rA = tid >> 2, qA = tid & 3;
    const int rB = tid >> 1, hB = tid & 1;
    const int rowA = rowTok ? rowTok[rA] : (mBase + rA);
    const float* Ap = A + (size_t)rowA * lda + qA * 8;
    const float* Bp = B + (size_t)(nBase + rB) * ldb + hB * 16;

    const int nch = K >> 5;
    const int awBase = rA * AW + qA * 4;
    const int bwBase = rB * AW + hB * 8;

    SmemT3* buf0 = (SmemT3*)smraw;
    SmemT3* buf1 = (SmemT3*)(smraw + sizeof(SmemT3));
    const uint32_t b0 = s2u(buf0);

    float4 va[2], vb[4];
    va[0] = *(const float4*)(Ap);
    va[1] = *(const float4*)(Ap + 4);
    #pragma unroll
    for (int j = 0; j < 4; j++) vb[j] = *(const float4*)(Bp + j * 4);
    cvt_store3(*buf0, awBase, bwBase, va, vb);
    if (nch > 1) {
        va[0] = *(const float4*)(Ap + 32);
        va[1] = *(const float4*)(Ap + 36);
        #pragma unroll
        for (int j = 0; j < 4; j++) vb[j] = *(const float4*)(Bp + 32 + j * 4);
    }
    __syncthreads();

    for (int t = 0; t < nch; t++) {
        const uint32_t co = b0 + (uint32_t)((t & 1) * (int)sizeof(SmemT3));
        const uint32_t aHiB = co, aLoB = co + 5120;
        const uint32_t bHiB = co + 10240, bLoB = co + 20480;
        mma_step3(aHiB, aLoB, bHiB, bLoB, 0, wm, wn, lane, acc);
        mma_step3(aHiB, aLoB, bHiB, bLoB, 1, wm, wn, lane, acc);
        if (t + 1 < nch) {
            SmemT3& nxt = ((t + 1) & 1) ? *buf1 : *buf0;
            cvt_store3(nxt, awBase, bwBase, va, vb);
            if (t + 2 < nch) {
                va[0] = *(const float4*)(Ap + (t+2)*32);
                va[1] = *(const float4*)(Ap + (t+2)*32 + 4);
                #pragma unroll
                for (int j = 0; j < 4; j++)
                    vb[j] = *(const float4*)(Bp + (t+2)*32 + j*4);
            }
        }
        __syncthreads();
    }
}

// ================= EXPERT core: fp16 single-pass (R12, numerics validated) ===
struct SmemT1 {
    uint32_t Ah[64*AW];
    uint32_t Bh[128*AW];
};  // 15360 bytes
#define DSMEM1 (2 * (int)sizeof(SmemT1))   // 30720

__device__ __forceinline__ uint32_t pack_h2(float a, float b) {
    __half2 h = __floats2half2_rn(a, b);
    return *reinterpret_cast<uint32_t*>(&h);
}

__device__ __forceinline__ void cvt_store1(SmemT1& s, int awBase, int bwBase,
                                           const float4* va, const float4* vb) {
    #pragma unroll
    for (int j = 0; j < 2; j++) {
        uint32_t h0 = pack_h2(va[j].x, va[j].y);
        uint32_t h1 = pack_h2(va[j].z, va[j].w);
        *(uint2*)&s.Ah[awBase + j*2] = make_uint2(h0, h1);
    }
    #pragma unroll
    for (int j = 0; j < 4; j++) {
        uint32_t h0 = pack_h2(vb[j].x, vb[j].y);
        uint32_t h1 = pack_h2(vb[j].z, vb[j].w);
        *(uint2*)&s.Bh[bwBase + j*2] = make_uint2(h0, h1);
    }
}

__device__ __forceinline__ void mma_step1(uint32_t aB, uint32_t bB,
                                          int ks, int wm, int wn, int lane,
                                          float (&acc)[8][4]) {
    const int kw = ks * 8;
    const int r = lane & 7, sub = lane >> 3;
    uint32_t ah[2][4], bh[2][4];
    #pragma unroll
    for (int mt = 0; mt < 2; mt++) {
        uint32_t off = (uint32_t)(((wm*32 + mt*16 + r + (sub&1)*8) * AW
                                   + kw + (sub>>1)*4) * 4);
        ldsm4(ah[mt], aB + off);
    }
    #pragma unroll
    for (int p = 0; p < 2; p++) {
        uint32_t off = (uint32_t)(((wn*32 + p*16 + r + (sub>>1)*8) * AW
                                   + kw + (sub&1)*4) * 4);
        ldsm4(bh[p], bB + off);
    }
    #pragma unroll
    for (int mt = 0; mt < 2; mt++)
        #pragma unroll
        for (int nt = 0; nt < 4; nt++) {
            uint32_t bh2[2] = { bh[nt>>1][(nt&1)*2], bh[nt>>1][(nt&1)*2+1] };
            mma_fp(acc[mt*4+nt], ah[mt], bh2);
        }
}

__device__ __forceinline__ void mma_gemm1(
    char* smraw,
    const float* __restrict__ A, int lda, const int* rowTok, int mBase,
    const float* __restrict__ B, int ldb, int nBase, int K,
    float (&acc)[8][4])
{
    const int tid  = threadIdx.x;
    const int lane = tid & 31, wid = tid >> 5;
    const int wm = wid >> 2, wn = wid & 3;

    const int rA = tid >> 2, qA = tid & 3;
    const int rB = tid >> 1, hB = tid & 1;
    const int rowA = rowTok ? rowTok[rA] : (mBase + rA);
    const float* Ap = A + (size_t)rowA * lda + qA * 8;
    const float* Bp = B + (size_t)(nBase + rB) * ldb + hB * 16;

    const int nch = K >> 5;
    const int awBase = rA * AW + qA * 4;
    const int bwBase = rB * AW + hB * 8;

    SmemT1* buf0 = (SmemT1*)smraw;
    SmemT1* buf1 = (SmemT1*)(smraw + sizeof(SmemT1));
    const uint32_t b0 = s2u(buf0);

    float4 va[2], vb[4];
    va[0] = *(const float4*)(Ap);
    va[1] = *(const float4*)(Ap + 4);
    #pragma unroll
    for (int j = 0; j < 4; j++) vb[j] = *(const float4*)(Bp + j * 4);
    cvt_store1(*buf0, awBase, bwBase, va, vb);
    if (nch > 1) {
        va[0] = *(const float4*)(Ap + 32);
        va[1] = *(const float4*)(Ap + 36);
        #pragma unroll
        for (int j = 0; j < 4; j++) vb[j] = *(const float4*)(Bp + 32 + j * 4);
    }
    __syncthreads();

    for (int t = 0; t < nch; t++) {
        const uint32_t co = b0 + (uint32_t)((t & 1) * (int)sizeof(SmemT1));
        const uint32_t aB = co, bB = co + 5120;
        mma_step1(aB, bB, 0, wm, wn, lane, acc);
        mma_step1(aB, bB, 1, wm, wn, lane, acc);
        if (t + 1 < nch) {
            SmemT1& nxt = ((t + 1) & 1) ? *buf1 : *buf0;
            cvt_store1(nxt, awBase, bwBase, va, vb);
            if (t + 2 < nch) {
                va[0] = *(const float4*)(Ap + (t+2)*32);
                va[1] = *(const float4*)(Ap + (t+2)*32 + 4);
                #pragma unroll
                for (int j = 0; j < 4; j++)
                    vb[j] = *(const float4*)(Bp + (t+2)*32 + j*4);
            }
        }
        __syncthreads();
    }
}

// ---------------- small utility kernels --------------------------------------
__global__ void zero_counts_kernel() {
    if (threadIdx.x < NE) g_ecnt[threadIdx.x] = 0;
}

__global__ void rmsnorm_kernel(const float* __restrict__ x,
                               const float* __restrict__ w,
                               float* __restrict__ out) {
    int row = blockIdx.x;
    const float* xr = x + (size_t)row * DIM;
    float ss = 0.f;
    for (int i = threadIdx.x; i < DIM; i += 256) { float v = xr[i]; ss += v * v; }
    __shared__ float red[256];
    red[threadIdx.x] = ss; __syncthreads();
    for (int st = 128; st > 0; st >>= 1) {
        if (threadIdx.x < st) red[threadIdx.x] += red[threadIdx.x + st];
        __syncthreads();
    }
    float rstd = rsqrtf(red[0] / (float)DIM + EPS);
    for (int i = threadIdx.x; i < DIM; i += 256)
        out[(size_t)row * DIM + i] = xr[i] * rstd * w[i];
}

__global__ void qknorm_rope_kernel(const float* __restrict__ qnw,
                                   const float* __restrict__ knw,
                                   const float* __restrict__ cosp,
                                   const float* __restrict__ sinp)
{
    int s = blockIdx.x, h2 = blockIdx.y, d = threadIdx.x;   // 128 threads
    float* ptr; const float* w;
    if (h2 < H) { ptr = g_qt + (size_t)h2       * S * HD + (size_t)s * HD; w = qnw; }
    else        { ptr = g_kt + (size_t)(h2 - H) * S * HD + (size_t)s * HD; w = knw; }
    __shared__ float row[HD];
    __shared__ float red[HD];
    float v = ptr[d];
    red[d] = v * v; __syncthreads();
    for (int st = 64; st > 0; st >>= 1) {
        if (d < st) red[d] += red[d + st];
        __syncthreads();
    }
    float rstd = rsqrtf(red[0] / (float)HD + EPS);
    row[d] = v * rstd * w[d];
    __syncthreads();
    float rot = (d < 64) ? -row[d + 64] : row[d - 64];
    ptr[d] = row[d] * cosp[s * HD + d] + rot * sinp[s * HD + d];
}

__global__ void softmax_kernel()
{
    int s = blockIdx.x, h = blockIdx.y, tid = threadIdx.x;   // 128 threads
    float* row = g_scores + (size_t)h * S * S + (size_t)s * S;
    int nk = s + 1;
    __shared__ float red[128];
    float m = -1e30f;
    for (int i = tid; i < nk; i += 128) m = fmaxf(m, row[i]);
    red[tid] = m; __syncthreads();
    for (int st = 64; st > 0; st >>= 1) {
        if (tid < st) red[tid] = fmaxf(red[tid], red[tid + st]);
        __syncthreads();
    }
    m = red[0]; __syncthreads();
    float sum = 0.f;
    for (int i = tid; i < nk; i += 128) {
        float e = expf(row[i] - m);
        row[i] = e; sum += e;
    }
    red[tid] = sum; __syncthreads();
    for (int st = 64; st > 0; st >>= 1) {
        if (tid < st) red[tid] += red[tid + st];
        __syncthreads();
    }
    float inv = 1.f / red[0];
    for (int i = tid; i < nk; i += 128) row[i] *= inv;
    for (int i = nk + tid; i < S; i += 128) row[i] = 0.f;
}

__global__ void router_kernel(const float* __restrict__ rw)
{
    int t = blockIdx.x, tid = threadIdx.x;   // 128 threads
    __shared__ float hrow[DIM];
    __shared__ float logits[NE];
    for (int i = tid; i < DIM; i += 128) hrow[i] = g_hn[(size_t)t * DIM + i];
    __syncthreads();
    if (tid < NE) {
        const float* r = rw + (size_t)tid * DIM;
        float acc = 0.f;
        for (int i = 0; i < DIM; i++) acc += hrow[i] * r[i];
        logits[tid] = acc;
    }
    __syncthreads();
    if (tid == 0) {
        float m = -1e30f;
        for (int e = 0; e < NE; e++) m = fmaxf(m, logits[e]);
        float pr[NE]; float sum = 0.f;
        for (int e = 0; e < NE; e++) { pr[e] = expf(logits[e] - m); sum += pr[e]; }
        float invs = 1.f / sum;
        for (int e = 0; e < NE; e++) pr[e] *= invs;
        int   ti[TOPK]; float tw[TOPK]; float wsum = 0.f;
        for (int kk = 0; kk < TOPK; kk++) {
            int best = 0; float bv = -1.f;
            for (int e = 0; e < NE; e++) if (pr[e] > bv) { bv = pr[e]; best = e; }
            ti[kk] = best; tw[kk] = bv; pr[best] = -2.f; wsum += bv;
        }
        float inv = 1.f / (wsum + 1e-20f);
        for (int kk = 0; kk < TOPK; kk++) {
            int e = ti[kk];
            int pos = atomicAdd(&g_ecnt[e], 1);
            g_etok[e * S + pos] = t;
            g_ew  [e * S + pos] = tw[kk] * inv;
        }
    }
}

__global__ void silu_kernel()
{
    int slot = blockIdx.x, e = blockIdx.y;
    if (slot >= g_ecnt[e]) return;
    size_t base = (size_t)(e * S + slot) * FF;
    for (int i = threadIdx.x; i < FF; i += 256) {
        float g = g_midg[base + i], u = g_midu[base + i];
        g_midg[base + i] = g / (1.f + expf(-g)) * u;
    }
}

// ================== trunk GEMM kernels (bf16 3-pass) ==========================

// QKV: grid (40, 8). x<32: q head; [32,36): k head; [36,40): v head (-> V^T).
__global__ __launch_bounds__(256) void qkv_kernel(
    const float* __restrict__ xn, const float* __restrict__ wq,
    const float* __restrict__ wk, const float* __restrict__ wv)
{
    extern __shared__ char smraw[];
    int nt = blockIdx.x, mBase = blockIdx.y * 64;
    const float* B; int head, fam;
    if (nt < H)           { B = wq; head = nt;          fam = 0; }
    else if (nt < H + HK) { B = wk; head = nt - H;      fam = 1; }
    else                  { B = wv; head = nt - H - HK; fam = 2; }
    float acc[8][4] = {};
    mma_gemm3(smraw, xn, DIM, nullptr, mBase, B, DIM, head * HD, DIM, acc);
    int lane = threadIdx.x & 31, wid = threadIdx.x >> 5;
    int wm = wid >> 2, wn = wid & 3;
    #pragma unroll
    for (int mt = 0; mt < 2; mt++)
        #pragma unroll
        for (int ntl = 0; ntl < 4; ntl++) {
            int r0  = mBase + wm*32 + mt*16 + (lane>>2);
            int col = wn*32 + ntl*8 + (lane&3)*2;
            float* a = acc[mt*4+ntl];
            if (fam == 0) {
                float* o = g_qt + (size_t)head*S*HD;
                *(float2*)&o[(size_t)r0*HD + col]     = make_float2(a[0], a[1]);
                *(float2*)&o[(size_t)(r0+8)*HD + col] = make_float2(a[2], a[3]);
            } else if (fam == 1) {
                float* o = g_kt + (size_t)head*S*HD;
                *(float2*)&o[(size_t)r0*HD + col]     = make_float2(a[0], a[1]);
                *(float2*)&o[(size_t)(r0+8)*HD + col] = make_float2(a[2], a[3]);
            } else {
                float* o = g_vtT + (size_t)head*HD*S;
                o[(size_t)col*S     + r0]     = a[0];
                o[(size_t)(col+1)*S + r0]     = a[1];
                o[(size_t)col*S     + r0 + 8] = a[2];
                o[(size_t)(col+1)*S + r0 + 8] = a[3];
            }
        }
}

// scores: grid (4, 8, 32). Skip fully-masked tiles.
__global__ __launch_bounds__(256) void scores_kernel()
{
    int h = blockIdx.z, mBase = blockIdx.y * 64, nBase = blockIdx.x * 128;
    if (nBase > mBase + 63) return;
    extern __shared__ char smraw[];
    int kvh = h / GRP;
    float acc[8][4] = {};
    mma_gemm3(smraw, g_qt + (size_t)h * S * HD, HD, nullptr, mBase,
              g_kt + (size_t)kvh * S * HD, HD, nBase, HD, acc);
    const float alpha = 0.08838834764831845f;   // 1/sqrt(128)
    float* C = g_scores + (size_t)h * S * S;
    int lane = threadIdx.x & 31, wid = threadIdx.x >> 5;
    int wm = wid >> 2, wn = wid & 3;
    #pragma unroll
    for (int mt = 0; mt < 2; mt++)
        #pragma unroll
        for (int ntl = 0; ntl < 4; ntl++) {
            int r0  = mBase + wm*32 + mt*16 + (lane>>2);
            int col = nBase + wn*32 + ntl*8 + (lane&3)*2;
            float* a = acc[mt*4+ntl];
            *(float2*)&C[(size_t)r0*S + col]     = make_float2(a[0]*alpha, a[1]*alpha);
            *(float2*)&C[(size_t)(r0+8)*S + col] = make_float2(a[2]*alpha, a[3]*alpha);
        }
}

// pv: grid (1, 8, 32). A = softmaxed scores, B = V^T.
__global__ __launch_bounds__(256) void pv_kernel()
{
    extern __shared__ char smraw[];
    int h = blockIdx.z, mBase = blockIdx.y * 64;
    int kvh = h / GRP;
    float acc[8][4] = {};
    mma_gemm3(smraw, g_scores + (size_t)h * S * S, S, nullptr, mBase,
              g_vtT + (size_t)kvh * HD * S, S, 0, S, acc);
    int lane = threadIdx.x & 31, wid = threadIdx.x >> 5;
    int wm = wid >> 2, wn = wid & 3;
    #pragma unroll
    for (int mt = 0; mt < 2; mt++)
        #pragma unroll
        for (int ntl = 0; ntl < 4; ntl++) {
            int r0  = mBase + wm*32 + mt*16 + (lane>>2);
            int col = h*HD + wn*32 + ntl*8 + (lane&3)*2;
            float* a = acc[mt*4+ntl];
            *(float2*)&g_attn[(size_t)r0*NQK + col]     = make_float2(a[0], a[1]);
            *(float2*)&g_attn[(size_t)(r0+8)*NQK + col] = make_float2(a[2], a[3]);
        }
}

// wo: grid (16, 8). out = attn @ wo^T + x  -> d_out
__global__ __launch_bounds__(256) void wo_kernel(
    const float* __restrict__ wo_w, const float* __restrict__ x,
    float* __restrict__ out)
{
    extern __shared__ char smraw[];
    int nBase = blockIdx.x * 128, mBase = blockIdx.y * 64;
    float acc[8][4] = {};
    mma_gemm3(smraw, g_attn, NQK, nullptr, mBase, wo_w, NQK, nBase, NQK, acc);
    int lane = threadIdx.x & 31, wid = threadIdx.x >> 5;
    int wm = wid >> 2, wn = wid & 3;
    #pragma unroll
    for (int mt = 0; mt < 2; mt++)
        #pragma unroll
        for (int ntl = 0; ntl < 4; ntl++) {
            int r0  = mBase + wm*32 + mt*16 + (lane>>2);
            int col = nBase + wn*32 + ntl*8 + (lane&3)*2;
            float* a = acc[mt*4+ntl];
            size_t i0 = (size_t)r0*DIM + col, i1 = (size_t)(r0+8)*DIM + col;
            float2 x0 = *(const float2*)&x[i0], x1 = *(const float2*)&x[i1];
            *(float2*)&out[i0] = make_float2(a[0] + x0.x, a[1] + x0.y);
            *(float2*)&out[i1] = make_float2(a[2] + x1.x, a[3] + x1.y);
        }
}

// ================== expert GEMM kernels (fp16 single-pass) ====================

// moe mid: grid (12, 8, 64). x<6 gate, else up. Gathered A rows.
__global__ __launch_bounds__(256) void moe_mid_kernel(
    const float* __restrict__ gate_w, const float* __restrict__ up_w)
{
    int e = blockIdx.z;
    int Me = g_ecnt[e];
    int rowBase = blockIdx.y * 64;
    if (rowBase >= Me) return;
    extern __shared__ char smraw[];
    __shared__ int tok[64];
    if (threadIdx.x < 64)
        tok[threadIdx.x] = g_etok[e * S + min(rowBase + (int)threadIdx.x, Me - 1)];
    __syncthreads();
    int xt = blockIdx.x;
    const float* B; float* C; int nBase;
    if (xt < 6) { B = gate_w + (size_t)e * FF * DIM; nBase = xt * 128;       C = g_midg; }
    else        { B = up_w   + (size_t)e * FF * DIM; nBase = (xt - 6) * 128; C = g_midu; }
    float acc[8][4] = {};
    mma_gemm1(smraw, g_hn, DIM, tok, 0, B, DIM, nBase, DIM, acc);
    int lane = threadIdx.x & 31, wid = threadIdx.x >> 5;
    int wm = wid >> 2, wn = wid & 3;
    #pragma unroll
    for (int mt = 0; mt < 2; mt++)
        #pragma unroll
        for (int ntl = 0; ntl < 4; ntl++) {
            int lr  = wm*32 + mt*16 + (lane>>2);
            int col = nBase + wn*32 + ntl*8 + (lane&3)*2;
            float* a = acc[mt*4+ntl];
            int s0 = rowBase + lr, s1 = s0 + 8;
            if (s0 < Me)
                *(float2*)&C[(size_t)(e*S + s0)*FF + col] = make_float2(a[0], a[1]);
            if (s1 < Me)
                *(float2*)&C[(size_t)(e*S + s1)*FF + col] = make_float2(a[2], a[3]);
        }
}

// moe down: grid (16, 8, 64). Weighted atomic scatter onto out.
__global__ __launch_bounds__(256) void moe_down_kernel(
    const float* __restrict__ down_w, float* __restrict__ out)
{
    int e = blockIdx.z;
    int Me = g_ecnt[e];
    int rowBase = blockIdx.y * 64;
    if (rowBase >= Me) return;
    extern __shared__ char smraw[];
    __shared__ int tok[64];
    __shared__ float wts[64];
    if (threadIdx.x < 64) {
        int sl = min(rowBase + (int)threadIdx.x, Me - 1);
        tok[threadIdx.x] = g_etok[e * S + sl];
        wts[threadIdx.x] = g_ew  [e * S + sl];
    }
    __syncthreads();
    int nBase = blockIdx.x * 128;
    float acc[8][4] = {};
    mma_gemm1(smraw, g_midg + (size_t)e * S * FF, FF, nullptr, rowBase,
              down_w + (size_t)e * DIM * FF, FF, nBase, FF, acc);
    int lane = threadIdx.x & 31, wid = threadIdx.x >> 5;
    int wm = wid >> 2, wn = wid & 3;
    #pragma unroll
    for (int mt = 0; mt < 2; mt++)
        #pragma unroll
        for (int ntl = 0; ntl < 4; ntl++) {
            int lr  = wm*32 + mt*16 + (lane>>2);
            int col = nBase + wn*32 + ntl*8 + (lane&3)*2;
            float* a = acc[mt*4+ntl];
            int s0 = rowBase + lr, s1 = s0 + 8;
            if (s0 < Me) {
                int t = tok[lr]; float w = wts[lr];
                atomicAdd(&out[(size_t)t*DIM + col],     a[0]*w);
                atomicAdd(&out[(size_t)t*DIM + col + 1], a[1]*w);
            }
            if (s1 < Me) {
                int t = tok[lr+8]; float w = wts[lr+8];
                atomicAdd(&out[(size_t)t*DIM + col],     a[2]*w);
                atomicAdd(&out[(size_t)t*DIM + col + 1], a[3]*w);
            }
        }
}

// ---------------- launch ------------------------------------------------------
extern "C" void kernel_launch(void* const* d_in, const int* in_sizes, int n_in,
                              void* d_out, int out_size)
{
    const float* x    = (const float*)d_in[0];
    const float* cosp = (const float*)d_in[1];
    const float* sinp = (const float*)d_in[2];
    const float* n1w  = (const float*)d_in[3];
    const float* wq   = (const float*)d_in[4];
    const float* wk   = (const float*)d_in[5];
    const float* wv   = (const float*)d_in[6];
    const float* wo_w = (const float*)d_in[7];
    const float* qnw  = (const float*)d_in[8];
    const float* knw  = (const float*)d_in[9];
    const float* n2w  = (const float*)d_in[10];
    const float* rw   = (const float*)d_in[11];
    const float* gw   = (const float*)d_in[12];
    const float* uw   = (const float*)d_in[13];
    const float* dw   = (const float*)d_in[14];
    float* out = (float*)d_out;

    cudaFuncSetAttribute(qkv_kernel,      cudaFuncAttributeMaxDynamicSharedMemorySize, DSMEM3);
    cudaFuncSetAttribute(scores_kernel,   cudaFuncAttributeMaxDynamicSharedMemorySize, DSMEM3);
    cudaFuncSetAttribute(pv_kernel,       cudaFuncAttributeMaxDynamicSharedMemorySize, DSMEM3);
    cudaFuncSetAttribute(wo_kernel,       cudaFuncAttributeMaxDynamicSharedMemorySize, DSMEM3);
    cudaFuncSetAttribute(moe_mid_kernel,  cudaFuncAttributeMaxDynamicSharedMemorySize, DSMEM1);
    cudaFuncSetAttribute(moe_down_kernel, cudaFuncAttributeMaxDynamicSharedMemorySize, DSMEM1);

    float *xn, *hn;
    cudaGetSymbolAddress((void**)&xn, g_xn);
    cudaGetSymbolAddress((void**)&hn, g_hn);

    zero_counts_kernel<<<1, 64>>>();
    rmsnorm_kernel<<<S, 256>>>(x, n1w, xn);
    qkv_kernel<<<dim3(H + 2*HK, S/64), 256, DSMEM3>>>(xn, wq, wk, wv);
    qknorm_rope_kernel<<<dim3(S, H + HK), HD>>>(qnw, knw, cosp, sinp);
    scores_kernel<<<dim3(S/128, S/64, H), 256, DSMEM3>>>();
    softmax_kernel<<<dim3(S, H), 128>>>();
    pv_kernel<<<dim3(1, S/64, H), 256, DSMEM3>>>();
    wo_kernel<<<dim3(DIM/128, S/64), 256, DSMEM3>>>(wo_w, x, out);
    rmsnorm_kernel<<<S, 256>>>(out, n2w, hn);
    router_kernel<<<S, 128>>>(rw);
    moe_mid_kernel<<<dim3(12, S/64, NE), 256, DSMEM1>>>(gw, uw);
    silu_kernel<<<dim3(S, NE), 256>>>();
    moe_down_kernel<<<dim3(DIM/128, S/64, NE), 256, DSMEM1>>>(dw, out);
}

// round 16
// speedup vs baseline: 2.2088x; 1.0024x over previous
#include <cuda_runtime.h>
#include <cuda_bf16.h>
#include <cuda_fp16.h>
#include <math.h>
#include <stdint.h>

#define S    512
#define DIM  2048
#define H    32
#define HK   4
#define HD   128
#define NQK  (H*HD)    // 4096
#define NKV  (HK*HD)   // 512
#define NE   64
#define TOPK 8
#define FF   768
#define EPS  1e-6f
#define GRP  (H/HK)    // 8

// GEMM tile config: BM=64, BN=128, BK=32, 256 threads (8 warps, warp tile 32x32)
#define AW 20   // smem words per row (16 data + 4 pad) -> conflict-free frag LDS
#define TW 132  // staging tile row stride (floats)

// ---------------- scratch (static device globals; no allocation) -------------
__device__ float g_xn[S*DIM];
__device__ float g_qt[(size_t)H*S*HD];      // [h][s][d]  (normalized+roped)
__device__ float g_kt[(size_t)HK*S*HD];     // [h][s][d]  (normalized+roped)
__device__ float g_vtT[(size_t)HK*HD*S];    // [h][d][s]  (transposed for PV)
__device__ float g_scores[(size_t)H*S*S];
__device__ float g_attn[S*NQK];             // [s][h*HD+d]
__device__ float g_hn[S*DIM];
__device__ float g_mid[(size_t)NE*S*FF];    // silu(gate)*up
__device__ int   g_ecnt[NE];
__device__ int   g_etok[NE*S];
__device__ float g_ew  [NE*S];

// ---------------- common helpers ---------------------------------------------
__device__ __forceinline__ uint32_t s2u(const void* p) {
    uint32_t a;
    asm("{ .reg .u64 t; cvta.to.shared.u64 t, %1; cvt.u32.u64 %0, t; }"
        : "=r"(a) : "l"(p));
    return a;
}

__device__ __forceinline__ void ldsm4(uint32_t* r, uint32_t addr) {
    asm volatile("ldmatrix.sync.aligned.m8n8.x4.shared.b16 {%0,%1,%2,%3}, [%4];"
                 : "=r"(r[0]), "=r"(r[1]), "=r"(r[2]), "=r"(r[3]) : "r"(addr));
}

__device__ __forceinline__ void mma_bf(float* c, const uint32_t* a, const uint32_t* b) {
    asm volatile(
        "mma.sync.aligned.m16n8k16.row.col.f32.bf16.bf16.f32 "
        "{%0,%1,%2,%3}, {%4,%5,%6,%7}, {%8,%9}, {%0,%1,%2,%3};"
        : "+f"(c[0]), "+f"(c[1]), "+f"(c[2]), "+f"(c[3])
        : "r"(a[0]), "r"(a[1]), "r"(a[2]), "r"(a[3]), "r"(b[0]), "r"(b[1]));
}
__device__ __forceinline__ void mma_fp(float* c, const uint32_t* a, const uint32_t* b) {
    asm volatile(
        "mma.sync.aligned.m16n8k16.row.col.f32.f16.f16.f32 "
        "{%0,%1,%2,%3}, {%4,%5,%6,%7}, {%8,%9}, {%0,%1,%2,%3};"
        : "+f"(c[0]), "+f"(c[1]), "+f"(c[2]), "+f"(c[3])
        : "r"(a[0]), "r"(a[1]), "r"(a[2]), "r"(a[3]), "r"(b[0]), "r"(b[1]));
}

// ================= TRUNK core: bf16 hi/lo 3-pass (proven 4.6e-6) =============
struct SmemT3 {
    uint32_t Ahi[64*AW];
    uint32_t Alo[64*AW];
    uint32_t Bhi[128*AW];
    uint32_t Blo[128*AW];
};  // 30720 bytes
#define DSMEM3 (2 * (int)sizeof(SmemT3))   // 61440

__device__ __forceinline__ void pack_hl(float a, float b, uint32_t& hi, uint32_t& lo) {
    __nv_bfloat162 h = __floats2bfloat162_rn(a, b);
    float ah = __bfloat162float(h.x), bh = __bfloat162float(h.y);
    __nv_bfloat162 l = __floats2bfloat162_rn(a - ah, b - bh);
    hi = *reinterpret_cast<uint32_t*>(&h);
    lo = *reinterpret_cast<uint32_t*>(&l);
}

__device__ __forceinline__ void cvt_store3(SmemT3& s, int awBase, int bwBase,
                                           const float4* va, const float4* vb) {
    #pragma unroll
    for (int j = 0; j < 2; j++) {
        uint32_t h0, l0, h1, l1;
        pack_hl(va[j].x, va[j].y, h0, l0);
        pack_hl(va[j].z, va[j].w, h1, l1);
        *(uint2*)&s.Ahi[awBase + j*2] = make_uint2(h0, h1);
        *(uint2*)&s.Alo[awBase + j*2] = make_uint2(l0, l1);
    }
    #pragma unroll
    for (int j = 0; j < 4; j++) {
        uint32_t h0, l0, h1, l1;
        pack_hl(vb[j].x, vb[j].y, h0, l0);
        pack_hl(vb[j].z, vb[j].w, h1, l1);
        *(uint2*)&s.Bhi[bwBase + j*2] = make_uint2(h0, h1);
        *(uint2*)&s.Blo[bwBase + j*2] = make_uint2(l0, l1);
    }
}

__device__ __forceinline__ void mma_step3(uint32_t aHiB, uint32_t aLoB,
                                          uint32_t bHiB, uint32_t bLoB,
                                          int ks, int wm, int wn, int lane,
                                          float (&acc)[8][4]) {
    const int kw = ks * 8;
    const int r = lane & 7, sub = lane >> 3;
    uint32_t ah[2][4], al[2][4], bh[2][4], bl[2][4];
    #pragma unroll
    for (int mt = 0; mt < 2; mt++) {
        uint32_t off = (uint32_t)(((wm*32 + mt*16 + r + (sub&1)*8) * AW
                                   + kw + (sub>>1)*4) * 4);
        ldsm4(ah[mt], aHiB + off);
        ldsm4(al[mt], aLoB + off);
    }
    #pragma unroll
    for (int p = 0; p < 2; p++) {
        uint32_t off = (uint32_t)(((wn*32 + p*16 + r + (sub>>1)*8) * AW
                                   + kw + (sub&1)*4) * 4);
        ldsm4(bh[p], bHiB + off);
        ldsm4(bl[p], bLoB + off);
    }
    #pragma unroll
    for (int mt = 0; mt < 2; mt++)
        #pragma unroll
        for (int nt = 0; nt < 4; nt++) {
            uint32_t bh2[2] = { bh[nt>>1][(nt&1)*2], bh[nt>>1][(nt&1)*2+1] };
            uint32_t bl2[2] = { bl[nt>>1][(nt&1)*2], bl[nt>>1][(nt&1)*2+1] };
            mma_bf(acc[mt*4+nt], ah[mt], bh2);
            mma_bf(acc[mt*4+nt], ah[mt], bl2);
            mma_bf(acc[mt*4+nt], al[mt], bh2);
        }
}

__device__ __forceinline__ void mma_gemm3(
    char* smraw,
    const float* __restrict__ A, int lda, const int* rowTok, int mBase,
    const float* __restrict__ B, int ldb, int nBase, int K,
    float (&acc)[8][4])
{
    const int tid  = threadIdx.x;
    const int lane = tid & 31, wid = tid >> 5;
    const int wm = wid >> 2, wn = wid & 3;

    const int rA = tid >> 2, qA = tid & 3;
    const int rB = tid >> 1, hB = tid & 1;
    const int rowA = rowTok ? rowTok[rA] : (mBase + rA);
    const float* Ap = A + (size_t)rowA * lda + qA * 8;
    const float* Bp = B + (size_t)(nBase + rB) * ldb + hB * 16;

    const int nch = K >> 5;
    const int awBase = rA * AW + qA * 4;
    const int bwBase = rB * AW + hB * 8;

    SmemT3* buf0 = (SmemT3*)smraw;
    SmemT3* buf1 = (SmemT3*)(smraw + sizeof(SmemT3));
    const uint32_t b0 = s2u(buf0);

    float4 va[2], vb[4];
    va[0] = *(const float4*)(Ap);
    va[1] = *(const float4*)(Ap + 4);
    #pragma unroll
    for (int j = 0; j < 4; j++) vb[j] = *(const float4*)(Bp + j * 4);
    cvt_store3(*buf0, awBase, bwBase, va, vb);
    if (nch > 1) {
        va[0] = *(const float4*)(Ap + 32);
        va[1] = *(const float4*)(Ap + 36);
        #pragma unroll
        for (int j = 0; j < 4; j++) vb[j] = *(const float4*)(Bp + 32 + j * 4);
    }
    __syncthreads();

    for (int t = 0; t < nch; t++) {
        const uint32_t co = b0 + (uint32_t)((t & 1) * (int)sizeof(SmemT3));
        const uint32_t aHiB = co, aLoB = co + 5120;
        const uint32_t bHiB = co + 10240, bLoB = co + 20480;
        mma_step3(aHiB, aLoB, bHiB, bLoB, 0, wm, wn, lane, acc);
        mma_step3(aHiB, aLoB, bHiB, bLoB, 1, wm, wn, lane, acc);
        if (t + 1 < nch) {
            SmemT3& nxt = ((t + 1) & 1) ? *buf1 : *buf0;
            cvt_store3(nxt, awBase, bwBase, va, vb);
            if (t + 2 < nch) {
                va[0] = *(const float4*)(Ap + (t+2)*32);
                va[1] = *(const float4*)(Ap + (t+2)*32 + 4);
                #pragma unroll
                for (int j = 0; j < 4; j++)
                    vb[j] = *(const float4*)(Bp + (t+2)*32 + j*4);
            }
        }
        __syncthreads();
    }
}

// ================= EXPERT core: fp16 single-pass (validated) =================
struct SmemT1 {
    uint32_t Ah[64*AW];
    uint32_t Bh[128*AW];
};  // 15360 bytes
#define DSMEM1 (2 * (int)sizeof(SmemT1))   // 30720
#define DSMEM_MID (DSMEM1 + 64*TW*4)       // + 33792 stage = 64512

__device__ __forceinline__ uint32_t pack_h2(float a, float b) {
    __half2 h = __floats2half2_rn(a, b);
    return *reinterpret_cast<uint32_t*>(&h);
}

__device__ __forceinline__ void cvt_store1(SmemT1& s, int awBase, int bwBase,
                                           const float4* va, const float4* vb) {
    #pragma unroll
    for (int j = 0; j < 2; j++) {
        uint32_t h0 = pack_h2(va[j].x, va[j].y);
        uint32_t h1 = pack_h2(va[j].z, va[j].w);
        *(uint2*)&s.Ah[awBase + j*2] = make_uint2(h0, h1);
    }
    #pragma unroll
    for (int j = 0; j < 4; j++) {
        uint32_t h0 = pack_h2(vb[j].x, vb[j].y);
        uint32_t h1 = pack_h2(vb[j].z, vb[j].w);
        *(uint2*)&s.Bh[bwBase + j*2] = make_uint2(h0, h1);
    }
}

__device__ __forceinline__ void mma_step1(uint32_t aB, uint32_t bB,
                                          int ks, int wm, int wn, int lane,
                                          float (&acc)[8][4]) {
    const int kw = ks * 8;
    const int r = lane & 7, sub = lane >> 3;
    uint32_t ah[2][4], bh[2][4];
    #pragma unroll
    for (int mt = 0; mt < 2; mt++) {
        uint32_t off = (uint32_t)(((wm*32 + mt*16 + r + (sub&1)*8) * AW
                                   + kw + (sub>>1)*4) * 4);
        ldsm4(ah[mt], aB + off);
    }
    #pragma unroll
    for (int p = 0; p < 2; p++) {
        uint32_t off = (uint32_t)(((wn*32 + p*16 + r + (sub>>1)*8) * AW
                                   + kw + (sub&1)*4) * 4);
        ldsm4(bh[p], bB + off);
    }
    #pragma unroll
    for (int mt = 0; mt < 2; mt++)
        #pragma unroll
        for (int nt = 0; nt < 4; nt++) {
            uint32_t bh2[2] = { bh[nt>>1][(nt&1)*2], bh[nt>>1][(nt&1)*2+1] };
            mma_fp(acc[mt*4+nt], ah[mt], bh2);
        }
}

__device__ __forceinline__ void mma_gemm1(
    char* smraw,
    const float* __restrict__ A, int lda, const int* rowTok, int mBase,
    const float* __restrict__ B, int ldb, int nBase, int K,
    float (&acc)[8][4])
{
    const int tid  = threadIdx.x;
    const int lane = tid & 31, wid = tid >> 5;
    const int wm = wid >> 2, wn = wid & 3;

    const int rA = tid >> 2, qA = tid & 3;
    const int rB = tid >> 1, hB = tid & 1;
    const int rowA = rowTok ? rowTok[rA] : (mBase + rA);
    const float* Ap = A + (size_t)rowA * lda + qA * 8;
    const float* Bp = B + (size_t)(nBase + rB) * ldb + hB * 16;

    const int nch = K >> 5;
    const int awBase = rA * AW + qA * 4;
    const int bwBase = rB * AW + hB * 8;

    SmemT1* buf0 = (SmemT1*)smraw;
    SmemT1* buf1 = (SmemT1*)(smraw + sizeof(SmemT1));
    const uint32_t b0 = s2u(buf0);

    float4 va[2], vb[4];
    va[0] = *(const float4*)(Ap);
    va[1] = *(const float4*)(Ap + 4);
    #pragma unroll
    for (int j = 0; j < 4; j++) vb[j] = *(const float4*)(Bp + j * 4);
    cvt_store1(*buf0, awBase, bwBase, va, vb);
    if (nch > 1) {
        va[0] = *(const float4*)(Ap + 32);
        va[1] = *(const float4*)(Ap + 36);
        #pragma unroll
        for (int j = 0; j < 4; j++) vb[j] = *(const float4*)(Bp + 32 + j * 4);
    }
    __syncthreads();

    for (int t = 0; t < nch; t++) {
        const uint32_t co = b0 + (uint32_t)((t & 1) * (int)sizeof(SmemT1));
        const uint32_t aB = co, bB = co + 5120;
        mma_step1(aB, bB, 0, wm, wn, lane, acc);
        mma_step1(aB, bB, 1, wm, wn, lane, acc);
        if (t + 1 < nch) {
            SmemT1& nxt = ((t + 1) & 1) ? *buf1 : *buf0;
            cvt_store1(nxt, awBase, bwBase, va, vb);
            if (t + 2 < nch) {
                va[0] = *(const float4*)(Ap + (t+2)*32);
                va[1] = *(const float4*)(Ap + (t+2)*32 + 4);
                #pragma unroll
                for (int j = 0; j < 4; j++)
                    vb[j] = *(const float4*)(Bp + (t+2)*32 + j*4);
            }
        }
        __syncthreads();
    }
}

// ---------------- small utility kernels --------------------------------------
__global__ void rmsnorm_kernel(const float* __restrict__ x,
                               const float* __restrict__ w,
                               float* __restrict__ out) {
    if (blockIdx.x == 0 && threadIdx.x < NE) g_ecnt[threadIdx.x] = 0;
    int row = blockIdx.x;
    const float* xr = x + (size_t)row * DIM;
    float ss = 0.f;
    for (int i = threadIdx.x; i < DIM; i += 256) { float v = xr[i]; ss += v * v; }
    __shared__ float red[256];
    red[threadIdx.x] = ss; __syncthreads();
    for (int st = 128; st > 0; st >>= 1) {
        if (threadIdx.x < st) red[threadIdx.x] += red[threadIdx.x + st];
        __syncthreads();
    }
    float rstd = rsqrtf(red[0] / (float)DIM + EPS);
    for (int i = threadIdx.x; i < DIM; i += 256)
        out[(size_t)row * DIM + i] = xr[i] * rstd * w[i];
}

__global__ void softmax_kernel()
{
    int s = blockIdx.x, h = blockIdx.y, tid = threadIdx.x;   // 128 threads
    float* row = g_scores + (size_t)h * S * S + (size_t)s * S;
    int nk = s + 1;
    __shared__ float red[128];
    float m = -1e30f;
    for (int i = tid; i < nk; i += 128) m = fmaxf(m, row[i]);
    red[tid] = m; __syncthreads();
    for (int st = 64; st > 0; st >>= 1) {
        if (tid < st) red[tid] = fmaxf(red[tid], red[tid + st]);
        __syncthreads();
    }
    m = red[0]; __syncthreads();
    float sum = 0.f;
    for (int i = tid; i < nk; i += 128) {
        float e = expf(row[i] - m);
        row[i] = e; sum += e;
    }
    red[tid] = sum; __syncthreads();
    for (int st = 64; st > 0; st >>= 1) {
        if (tid < st) red[tid] += red[tid + st];
        __syncthreads();
    }
    float inv = 1.f / red[0];
    for (int i = tid; i < nk; i += 128) row[i] *= inv;
    for (int i = nk + tid; i < S; i += 128) row[i] = 0.f;
}

__global__ void router_kernel(const float* __restrict__ rw)
{
    int t = blockIdx.x, tid = threadIdx.x;   // 128 threads
    __shared__ float hrow[DIM];
    __shared__ float logits[NE];
    for (int i = tid; i < DIM; i += 128) hrow[i] = g_hn[(size_t)t * DIM + i];
    __syncthreads();
    if (tid < NE) {
        const float* r = rw + (size_t)tid * DIM;
        float acc = 0.f;
        for (int i = 0; i < DIM; i++) acc += hrow[i] * r[i];
        logits[tid] = acc;
    }
    __syncthreads();
    if (tid == 0) {
        float m = -1e30f;
        for (int e = 0; e < NE; e++) m = fmaxf(m, logits[e]);
        float pr[NE]; float sum = 0.f;
        for (int e = 0; e < NE; e++) { pr[e] = expf(logits[e] - m); sum += pr[e]; }
        float invs = 1.f / sum;
        for (int e = 0; e < NE; e++) pr[e] *= invs;
        int   ti[TOPK]; float tw[TOPK]; float wsum = 0.f;
        for (int kk = 0; kk < TOPK; kk++) {
            int best = 0; float bv = -1.f;
            for (int e = 0; e < NE; e++) if (pr[e] > bv) { bv = pr[e]; best = e; }
            ti[kk] = best; tw[kk] = bv; pr[best] = -2.f; wsum += bv;
        }
        float inv = 1.f / (wsum + 1e-20f);
        for (int kk = 0; kk < TOPK; kk++) {
            int e = ti[kk];
            int pos = atomicAdd(&g_ecnt[e], 1);
            g_etok[e * S + pos] = t;
            g_ew  [e * S + pos] = tw[kk] * inv;
        }
    }
}

// ================== trunk GEMM kernels (bf16 3-pass) ==========================

// QKV: grid (40, 8). q/k heads: fused per-head RMSNorm+RoPE epilogue.
__global__ __launch_bounds__(256) void qkv_kernel(
    const float* __restrict__ xn, const float* __restrict__ wq,
    const float* __restrict__ wk, const float* __restrict__ wv,
    const float* __restrict__ qnw, const float* __restrict__ knw,
    const float* __restrict__ cosp, const float* __restrict__ sinp)
{
    extern __shared__ char smraw[];
    int nt = blockIdx.x, mBase = blockIdx.y * 64;
    const float* B; int head, fam;
    if (nt < H)           { B = wq; head = nt;          fam = 0; }
    else if (nt < H + HK) { B = wk; head = nt - H;      fam = 1; }
    else                  { B = wv; head = nt - H - HK; fam = 2; }
    float acc[8][4] = {};
    mma_gemm3(smraw, xn, DIM, nullptr, mBase, B, DIM, head * HD, DIM, acc);
    int tid = threadIdx.x;
    int lane = tid & 31, wid = tid >> 5;
    int wm = wid >> 2, wn = wid & 3;

    if (fam == 2) {   // V: plain transposed store
        float* o = g_vtT + (size_t)head*HD*S;
        #pragma unroll
        for (int mt = 0; mt < 2; mt++)
            #pragma unroll
            for (int ntl = 0; ntl < 4; ntl++) {
                int r0  = mBase + wm*32 + mt*16 + (lane>>2);
                int col = wn*32 + ntl*8 + (lane&3)*2;
                float* a = acc[mt*4+ntl];
                o[(size_t)col*S     + r0]     = a[0];
                o[(size_t)(col+1)*S + r0]     = a[1];
                o[(size_t)col*S     + r0 + 8] = a[2];
                o[(size_t)(col+1)*S + r0 + 8] = a[3];
            }
        return;
    }

    // q/k: stage tile, per-row rmsnorm, rope, store.
    float* tile = (float*)smraw;   // 64 x TW floats (GEMM buffers are dead)
    #pragma unroll
    for (int mt = 0; mt < 2; mt++)
        #pragma unroll
        for (int ntl = 0; ntl < 4; ntl++) {
            int r  = wm*32 + mt*16 + (lane>>2);
            int c  = wn*32 + ntl*8 + (lane&3)*2;
            float* a = acc[mt*4+ntl];
            tile[r*TW + c] = a[0];     tile[r*TW + c + 1] = a[1];
            tile[(r+8)*TW + c] = a[2]; tile[(r+8)*TW + c + 1] = a[3];
        }
    __syncthreads();

    const float* w = (fam == 0) ? qnw : knw;
    int row = tid >> 2, part = tid & 3;         // 4 threads per row
    float ss = 0.f;
    #pragma unroll
    for (int i = 0; i < 32; i++) {
        float v = tile[row*TW + part*32 + i];
        ss += v * v;
    }
    ss += __shfl_xor_sync(0xffffffffu, ss, 1);
    ss += __shfl_xor_sync(0xffffffffu, ss, 2);
    float rstd = rsqrtf(ss / (float)HD + EPS);
    #pragma unroll
    for (int i = 0; i < 32; i++) {
        int d = part*32 + i;
        tile[row*TW + d] *= rstd * w[d];
    }
    __syncthreads();

    int s = mBase + row;
    float* o = ((fam == 0) ? g_qt + (size_t)head*S*HD
                           : g_kt + (size_t)head*S*HD) + (size_t)s * HD;
    const float* cp = cosp + (size_t)s * HD;
    const float* sp = sinp + (size_t)s * HD;
    #pragma unroll
    for (int i = 0; i < 32; i++) {
        int d = part*32 + i;
        float n = tile[row*TW + d];
        float rot = (d < 64) ? -tile[row*TW + d + 64] : tile[row*TW + d - 64];
        o[d] = n * cp[d] + rot * sp[d];
    }
}

// scores: grid (4, 8, 32). Skip fully-masked tiles.
__global__ __launch_bounds__(256) void scores_kernel()
{
    int h = blockIdx.z, mBase = blockIdx.y * 64, nBase = blockIdx.x * 128;
    if (nBase > mBase + 63) return;
    extern __shared__ char smraw[];
    int kvh = h / GRP;
    float acc[8][4] = {};
    mma_gemm3(smraw, g_qt + (size_t)h * S * HD, HD, nullptr, mBase,
              g_kt + (size_t)kvh * S * HD, HD, nBase, HD, acc);
    const float alpha = 0.08838834764831845f;   // 1/sqrt(128)
    float* C = g_scores + (size_t)h * S * S;
    int lane = threadIdx.x & 31, wid = threadIdx.x >> 5;
    int wm = wid >> 2, wn = wid & 3;
    #pragma unroll
    for (int mt = 0; mt < 2; mt++)
        #pragma unroll
        for (int ntl = 0; ntl < 4; ntl++) {
            int r0  = mBase + wm*32 + mt*16 + (lane>>2);
            int col = nBase + wn*32 + ntl*8 + (lane&3)*2;
            float* a = acc[mt*4+ntl];
            *(float2*)&C[(size_t)r0*S + col]     = make_float2(a[0]*alpha, a[1]*alpha);
            *(float2*)&C[(size_t)(r0+8)*S + col] = make_float2(a[2]*alpha, a[3]*alpha);
        }
}

// pv: grid (1, 8, 32). A = softmaxed scores, B = V^T.
__global__ __launch_bounds__(256) void pv_kernel()
{
    extern __shared__ char smraw[];
    int h = blockIdx.z, mBase = blockIdx.y * 64;
    int kvh = h / GRP;
    float acc[8][4] = {};
    mma_gemm3(smraw, g_scores + (size_t)h * S * S, S, nullptr, mBase,
              g_vtT + (size_t)kvh * HD * S, S, 0, S, acc);
    int lane = threadIdx.x & 31, wid = threadIdx.x >> 5;
    int wm = wid >> 2, wn = wid & 3;
    #pragma unroll
    for (int mt = 0; mt < 2; mt++)
        #pragma unroll
        for (int ntl = 0; ntl < 4; ntl++) {
            int r0  = mBase + wm*32 + mt*16 + (lane>>2);
            int col = h*HD + wn*32 + ntl*8 + (lane&3)*2;
            float* a = acc[mt*4+ntl];
            *(float2*)&g_attn[(size_t)r0*NQK + col]     = make_float2(a[0], a[1]);
            *(float2*)&g_attn[(size_t)(r0+8)*NQK + col] = make_float2(a[2], a[3]);
        }
}

// wo: grid (16, 8). out = attn @ wo^T + x  -> d_out
__global__ __launch_bounds__(256) void wo_kernel(
    const float* __restrict__ wo_w, const float* __restrict__ x,
    float* __restrict__ out)
{
    extern __shared__ char smraw[];
    int nBase = blockIdx.x * 128, mBase = blockIdx.y * 64;
    float acc[8][4] = {};
    mma_gemm3(smraw, g_attn, NQK, nullptr, mBase, wo_w, NQK, nBase, NQK, acc);
    int lane = threadIdx.x & 31, wid = threadIdx.x >> 5;
    int wm = wid >> 2, wn = wid & 3;
    #pragma unroll
    for (int mt = 0; mt < 2; mt++)
        #pragma unroll
        for (int ntl = 0; ntl < 4; ntl++) {
            int r0  = mBase + wm*32 + mt*16 + (lane>>2);
            int col = nBase + wn*32 + ntl*8 + (lane&3)*2;
            float* a = acc[mt*4+ntl];
            size_t i0 = (size_t)r0*DIM + col, i1 = (size_t)(r0+8)*DIM + col;
            float2 x0 = *(const float2*)&x[i0], x1 = *(const float2*)&x[i1];
            *(float2*)&out[i0] = make_float2(a[0] + x0.x, a[1] + x0.y);
            *(float2*)&out[i1] = make_float2(a[2] + x1.x, a[3] + x1.y);
        }
}

// ================== expert GEMM kernels (fp16 single-pass) ====================

// moe mid: grid (6, 8, 64). Per block: gate GEMM -> stage, up GEMM, silu*u.
__global__ __launch_bounds__(256) void moe_mid_kernel(
    const float* __restrict__ gate_w, const float* __restrict__ up_w)
{
    int e = blockIdx.z;
    int Me = g_ecnt[e];
    int rowBase = blockIdx.y * 64;
    if (rowBase >= Me) return;
    extern __shared__ char smraw[];
    __shared__ int tok[64];
    if (threadIdx.x < 64)
        tok[threadIdx.x] = g_etok[e * S + min(rowBase + (int)threadIdx.x, Me - 1)];
    __syncthreads();
    int nBase = blockIdx.x * 128;

    int lane = threadIdx.x & 31, wid = threadIdx.x >> 5;
    int wm = wid >> 2, wn = wid & 3;
    float* stage = (float*)(smraw + DSMEM1);   // 64 x TW floats

    // pass 1: gate
    float acc[8][4] = {};
    mma_gemm1(smraw, g_hn, DIM, tok, 0, gate_w + (size_t)e * FF * DIM,
              DIM, nBase, DIM, acc);
    #pragma unroll
    for (int mt = 0; mt < 2; mt++)
        #pragma unroll
        for (int ntl = 0; ntl < 4; ntl++) {
            int r = wm*32 + mt*16 + (lane>>2);
            int c = wn*32 + ntl*8 + (lane&3)*2;
            float* a = acc[mt*4+ntl];
            stage[r*TW + c] = a[0];     stage[r*TW + c + 1] = a[1];
            stage[(r+8)*TW + c] = a[2]; stage[(r+8)*TW + c + 1] = a[3];
        }
    // no sync needed: each thread re-reads only its own staged values, and the
    // stage area is disjoint from the GEMM buffers the second pass uses.

    // pass 2: up (reuse acc)
    #pragma unroll
    for (int i = 0; i < 8; i++)
        #pragma unroll
        for (int j = 0; j < 4; j++) acc[i][j] = 0.f;
    mma_gemm1(smraw, g_hn, DIM, tok, 0, up_w + (size_t)e * FF * DIM,
              DIM, nBase, DIM, acc);

    // epilogue: mid = silu(gate) * up
    #pragma unroll
    for (int mt = 0; mt < 2; mt++)
        #pragma unroll
        for (int ntl = 0; ntl < 4; ntl++) {
            int lr  = wm*32 + mt*16 + (lane>>2);
            int lc  = wn*32 + ntl*8 + (lane&3)*2;
            int col = nBase + lc;
            float* a = acc[mt*4+ntl];
            int s0 = rowBase + lr, s1 = s0 + 8;
            if (s0 < Me) {
                float gg0 = stage[lr*TW + lc], gg1 = stage[lr*TW + lc + 1];
                float m0 = gg0 / (1.f + expf(-gg0)) * a[0];
                float m1 = gg1 / (1.f + expf(-gg1)) * a[1];
                *(float2*)&g_mid[(size_t)(e*S + s0)*FF + col] = make_float2(m0, m1);
            }
            if (s1 < Me) {
                float gg2 = stage[(lr+8)*TW + lc], gg3 = stage[(lr+8)*TW + lc + 1];
                float m2 = gg2 / (1.f + expf(-gg2)) * a[2];
                float m3 = gg3 / (1.f + expf(-gg3)) * a[3];
                *(float2*)&g_mid[(size_t)(e*S + s1)*FF + col] = make_float2(m2, m3);
            }
        }
}

// moe down: grid (16, 8, 64). Weighted atomic scatter onto out.
__global__ __launch_bounds__(256) void moe_down_kernel(
    const float* __restrict__ down_w, float* __restrict__ out)
{
    int e = blockIdx.z;
    int Me = g_ecnt[e];
    int rowBase = blockIdx.y * 64;
    if (rowBase >= Me) return;
    extern __shared__ char smraw[];
    __shared__ int tok[64];
    __shared__ float wts[64];
    if (threadIdx.x < 64) {
        int sl = min(rowBase + (int)threadIdx.x, Me - 1);
        tok[threadIdx.x] = g_etok[e * S + sl];
        wts[threadIdx.x] = g_ew  [e * S + sl];
    }
    __syncthreads();
    int nBase = blockIdx.x * 128;
    float acc[8][4] = {};
    mma_gemm1(smraw, g_mid + (size_t)e * S * FF, FF, nullptr, rowBase,
              down_w + (size_t)e * DIM * FF, FF, nBase, FF, acc);
    int lane = threadIdx.x & 31, wid = threadIdx.x >> 5;
    int wm = wid >> 2, wn = wid & 3;
    #pragma unroll
    for (int mt = 0; mt < 2; mt++)
        #pragma unroll
        for (int ntl = 0; ntl < 4; ntl++) {
            int lr  = wm*32 + mt*16 + (lane>>2);
            int col = nBase + wn*32 + ntl*8 + (lane&3)*2;
            float* a = acc[mt*4+ntl];
            int s0 = rowBase + lr, s1 = s0 + 8;
            if (s0 < Me) {
                int t = tok[lr]; float w = wts[lr];
                atomicAdd(&out[(size_t)t*DIM + col],     a[0]*w);
                atomicAdd(&out[(size_t)t*DIM + col + 1], a[1]*w);
            }
            if (s1 < Me) {
                int t = tok[lr+8]; float w = wts[lr+8];
                atomicAdd(&out[(size_t)t*DIM + col],     a[2]*w);
                atomicAdd(&out[(size_t)t*DIM + col + 1], a[3]*w);
            }
        }
}

// ---------------- launch ------------------------------------------------------
extern "C" void kernel_launch(void* const* d_in, const int* in_sizes, int n_in,
                              void* d_out, int out_size)
{
    const float* x    = (const float*)d_in[0];
    const float* cosp = (const float*)d_in[1];
    const float* sinp = (const float*)d_in[2];
    const float* n1w  = (const float*)d_in[3];
    const float* wq   = (const float*)d_in[4];
    const float* wk   = (const float*)d_in[5];
    const float* wv   = (const float*)d_in[6];
    const float* wo_w = (const float*)d_in[7];
    const float* qnw  = (const float*)d_in[8];
    const float* knw  = (const float*)d_in[9];
    const float* n2w  = (const float*)d_in[10];
    const float* rw   = (const float*)d_in[11];
    const float* gw   = (const float*)d_in[12];
    const float* uw   = (const float*)d_in[13];
    const float* dw   = (const float*)d_in[14];
    float* out = (float*)d_out;

    cudaFuncSetAttribute(qkv_kernel,      cudaFuncAttributeMaxDynamicSharedMemorySize, DSMEM3);
    cudaFuncSetAttribute(scores_kernel,   cudaFuncAttributeMaxDynamicSharedMemorySize, DSMEM3);
    cudaFuncSetAttribute(pv_kernel,       cudaFuncAttributeMaxDynamicSharedMemorySize, DSMEM3);
    cudaFuncSetAttribute(wo_kernel,       cudaFuncAttributeMaxDynamicSharedMemorySize, DSMEM3);
    cudaFuncSetAttribute(moe_mid_kernel,  cudaFuncAttributeMaxDynamicSharedMemorySize, DSMEM_MID);
    cudaFuncSetAttribute(moe_down_kernel, cudaFuncAttributeMaxDynamicSharedMemorySize, DSMEM1);

    float *xn, *hn;
    cudaGetSymbolAddress((void**)&xn, g_xn);
    cudaGetSymbolAddress((void**)&hn, g_hn);

    rmsnorm_kernel<<<S, 256>>>(x, n1w, xn);
    qkv_kernel<<<dim3(H + 2*HK, S/64), 256, DSMEM3>>>(xn, wq, wk, wv,
                                                      qnw, knw, cosp, sinp);
    scores_kernel<<<dim3(S/128, S/64, H), 256, DSMEM3>>>();
    softmax_kernel<<<dim3(S, H), 128>>>();
    pv_kernel<<<dim3(1, S/64, H), 256, DSMEM3>>>();
    wo_kernel<<<dim3(DIM/128, S/64), 256, DSMEM3>>>(wo_w, x, out);
    rmsnorm_kernel<<<S, 256>>>(out, n2w, hn);
    router_kernel<<<S, 128>>>(rw);
    moe_mid_kernel<<<dim3(6, S/64, NE), 256, DSMEM_MID>>>(gw, uw);
    moe_down_kernel<<<dim3(DIM/128, S/64, NE), 256, DSMEM1>>>(dw, out);
}

// round 17
// speedup vs baseline: 2.2569x; 1.0218x over previous
#include <cuda_runtime.h>
#include <cuda_bf16.h>
#include <cuda_fp16.h>
#include <math.h>
#include <stdint.h>

#define S    512
#define DIM  2048
#define H    32
#define HK   4
#define HD   128
#define NQK  (H*HD)    // 4096
#define NKV  (HK*HD)   // 512
#define NE   64
#define TOPK 8
#define FF   768
#define EPS  1e-6f
#define GRP  (H/HK)    // 8

// GEMM tile config: BM=64, BN=128, BK=32, 256 threads (8 warps, warp tile 32x32)
#define AW 20   // smem words per row (16 data + 4 pad) -> conflict-free frag LDS
#define TW 132  // staging tile row stride (floats)

// ---------------- scratch (static device globals; no allocation) -------------
__device__ float  g_xn[S*DIM];
__device__ float  g_qt[(size_t)H*S*HD];     // [h][s][d]  (normalized+roped)
__device__ float  g_kt[(size_t)HK*S*HD];    // [h][s][d]  (normalized+roped)
__device__ float  g_vtT[(size_t)HK*HD*S];   // [h][d][s]  (transposed for PV)
__device__ float  g_scores[(size_t)H*S*S];  // raw scaled logits (causal part)
__device__ float  g_attn[S*NQK];            // [s][h*HD+d]
__device__ __half g_hn16[S*DIM];            // fp16 hn for expert A-operand
__device__ __half g_mid[(size_t)NE*S*FF];   // silu(gate)*up, fp16
__device__ int    g_ecnt[NE];
__device__ int    g_etok[NE*S];
__device__ float  g_ew  [NE*S];

// ---------------- common helpers ---------------------------------------------
__device__ __forceinline__ uint32_t s2u(const void* p) {
    uint32_t a;
    asm("{ .reg .u64 t; cvta.to.shared.u64 t, %1; cvt.u32.u64 %0, t; }"
        : "=r"(a) : "l"(p));
    return a;
}

__device__ __forceinline__ void ldsm4(uint32_t* r, uint32_t addr) {
    asm volatile("ldmatrix.sync.aligned.m8n8.x4.shared.b16 {%0,%1,%2,%3}, [%4];"
                 : "=r"(r[0]), "=r"(r[1]), "=r"(r[2]), "=r"(r[3]) : "r"(addr));
}

__device__ __forceinline__ void mma_bf(float* c, const uint32_t* a, const uint32_t* b) {
    asm volatile(
        "mma.sync.aligned.m16n8k16.row.col.f32.bf16.bf16.f32 "
        "{%0,%1,%2,%3}, {%4,%5,%6,%7}, {%8,%9}, {%0,%1,%2,%3};"
        : "+f"(c[0]), "+f"(c[1]), "+f"(c[2]), "+f"(c[3])
        : "r"(a[0]), "r"(a[1]), "r"(a[2]), "r"(a[3]), "r"(b[0]), "r"(b[1]));
}
__device__ __forceinline__ void mma_fp(float* c, const uint32_t* a, const uint32_t* b) {
    asm volatile(
        "mma.sync.aligned.m16n8k16.row.col.f32.f16.f16.f32 "
        "{%0,%1,%2,%3}, {%4,%5,%6,%7}, {%8,%9}, {%0,%1,%2,%3};"
        : "+f"(c[0]), "+f"(c[1]), "+f"(c[2]), "+f"(c[3])
        : "r"(a[0]), "r"(a[1]), "r"(a[2]), "r"(a[3]), "r"(b[0]), "r"(b[1]));
}

// ================= TRUNK core: bf16 hi/lo 3-pass (proven 4.6e-6) =============
struct SmemT3 {
    uint32_t Ahi[64*AW];
    uint32_t Alo[64*AW];
    uint32_t Bhi[128*AW];
    uint32_t Blo[128*AW];
};  // 30720 bytes
#define DSMEM3 (2 * (int)sizeof(SmemT3))   // 61440
#define DSMEM_PV (DSMEM3 + 512)            // + per-row m/inv

__device__ __forceinline__ void pack_hl(float a, float b, uint32_t& hi, uint32_t& lo) {
    __nv_bfloat162 h = __floats2bfloat162_rn(a, b);
    float ah = __bfloat162float(h.x), bh = __bfloat162float(h.y);
    __nv_bfloat162 l = __floats2bfloat162_rn(a - ah, b - bh);
    hi = *reinterpret_cast<uint32_t*>(&h);
    lo = *reinterpret_cast<uint32_t*>(&l);
}

__device__ __forceinline__ void cvt_store3(SmemT3& s, int awBase, int bwBase,
                                           const float4* va, const float4* vb) {
    #pragma unroll
    for (int j = 0; j < 2; j++) {
        uint32_t h0, l0, h1, l1;
        pack_hl(va[j].x, va[j].y, h0, l0);
        pack_hl(va[j].z, va[j].w, h1, l1);
        *(uint2*)&s.Ahi[awBase + j*2] = make_uint2(h0, h1);
        *(uint2*)&s.Alo[awBase + j*2] = make_uint2(l0, l1);
    }
    #pragma unroll
    for (int j = 0; j < 4; j++) {
        uint32_t h0, l0, h1, l1;
        pack_hl(vb[j].x, vb[j].y, h0, l0);
        pack_hl(vb[j].z, vb[j].w, h1, l1);
        *(uint2*)&s.Bhi[bwBase + j*2] = make_uint2(h0, h1);
        *(uint2*)&s.Blo[bwBase + j*2] = make_uint2(l0, l1);
    }
}

__device__ __forceinline__ void mma_step3(uint32_t aHiB, uint32_t aLoB,
                                          uint32_t bHiB, uint32_t bLoB,
                                          int ks, int wm, int wn, int lane,
                                          float (&acc)[8][4]) {
    const int kw = ks * 8;
    const int r = lane & 7, sub = lane >> 3;
    uint32_t ah[2][4], al[2][4], bh[2][4], bl[2][4];
    #pragma unroll
    for (int mt = 0; mt < 2; mt++) {
        uint32_t off = (uint32_t)(((wm*32 + mt*16 + r + (sub&1)*8) * AW
                                   + kw + (sub>>1)*4) * 4);
        ldsm4(ah[mt], aHiB + off);
        ldsm4(al[mt], aLoB + off);
    }
    #pragma unroll
    for (int p = 0; p < 2; p++) {
        uint32_t off = (uint32_t)(((wn*32 + p*16 + r + (sub>>1)*8) * AW
                                   + kw + (sub&1)*4) * 4);
        ldsm4(bh[p], bHiB + off);
        ldsm4(bl[p], bLoB + off);
    }
    #pragma unroll
    for (int mt = 0; mt < 2; mt++)
        #pragma unroll
        for (int nt = 0; nt < 4; nt++) {
            uint32_t bh2[2] = { bh[nt>>1][(nt&1)*2], bh[nt>>1][(nt&1)*2+1] };
            uint32_t bl2[2] = { bl[nt>>1][(nt&1)*2], bl[nt>>1][(nt&1)*2+1] };
            mma_bf(acc[mt*4+nt], ah[mt], bh2);
            mma_bf(acc[mt*4+nt], ah[mt], bl2);
            mma_bf(acc[mt*4+nt], al[mt], bh2);
        }
}

__device__ __forceinline__ void mma_gemm3(
    char* smraw,
    const float* __restrict__ A, int lda, const int* rowTok, int mBase,
    const float* __restrict__ B, int ldb, int nBase, int K,
    float (&acc)[8][4])
{
    const int tid  = threadIdx.x;
    const int lane = tid & 31, wid = tid >> 5;
    const int wm = wid >> 2, wn = wid & 3;

    const int rA = tid >> 2, qA = tid & 3;
    const int rB = tid >> 1, hB = tid & 1;
    const int rowA = rowTok ? rowTok[rA] : (mBase + rA);
    const float* Ap = A + (size_t)rowA * lda + qA * 8;
    const float* Bp = B + (size_t)(nBase + rB) * ldb + hB * 16;

    const int nch = K >> 5;
    const int awBase = rA * AW + qA * 4;
    const int bwBase = rB * AW + hB * 8;

    SmemT3* buf0 = (SmemT3*)smraw;
    SmemT3* buf1 = (SmemT3*)(smraw + sizeof(SmemT3));
    const uint32_t b0 = s2u(buf0);

    float4 va[2], vb[4];
    va[0] = *(const float4*)(Ap);
    va[1] = *(const float4*)(Ap + 4);
    #pragma unroll
    for (int j = 0; j < 4; j++) vb[j] = *(const float4*)(Bp + j * 4);
    cvt_store3(*buf0, awBase, bwBase, va, vb);
    if (nch > 1) {
        va[0] = *(const float4*)(Ap + 32);
        va[1] = *(const float4*)(Ap + 36);
        #pragma unroll
        for (int j = 0; j < 4; j++) vb[j] = *(const float4*)(Bp + 32 + j * 4);
    }
    __syncthreads();

    for (int t = 0; t < nch; t++) {
        const uint32_t co = b0 + (uint32_t)((t & 1) * (int)sizeof(SmemT3));
        const uint32_t aHiB = co, aLoB = co + 5120;
        const uint32_t bHiB = co + 10240, bLoB = co + 20480;
        mma_step3(aHiB, aLoB, bHiB, bLoB, 0, wm, wn, lane, acc);
        mma_step3(aHiB, aLoB, bHiB, bLoB, 1, wm, wn, lane, acc);
        if (t + 1 < nch) {
            SmemT3& nxt = ((t + 1) & 1) ? *buf1 : *buf0;
            cvt_store3(nxt, awBase, bwBase, va, vb);
            if (t + 2 < nch) {
                va[0] = *(const float4*)(Ap + (t+2)*32);
                va[1] = *(const float4*)(Ap + (t+2)*32 + 4);
                #pragma unroll
                for (int j = 0; j < 4; j++)
                    vb[j] = *(const float4*)(Bp + (t+2)*32 + j*4);
            }
        }
        __syncthreads();
    }
}

// ---- trunk core variant for PV: applies softmax (exp(a-m)*inv, causal mask)
// to A elements during the fp32->bf16 conversion. smM/smI hold per-row m, 1/sum.
__device__ __forceinline__ void mma_gemm3sm(
    char* smraw,
    const float* __restrict__ A, int lda, int mBase,
    const float* __restrict__ B, int ldb, int K,
    const float* smM, const float* smI,
    float (&acc)[8][4])
{
    const int tid  = threadIdx.x;
    const int lane = tid & 31, wid = tid >> 5;
    const int wm = wid >> 2, wn = wid & 3;

    const int rA = tid >> 2, qA = tid & 3;
    const int rB = tid >> 1, hB = tid & 1;
    const float* Ap = A + (size_t)(mBase + rA) * lda + qA * 8;
    const float* Bp = B + (size_t)rB * ldb + hB * 16;

    const int nch = K >> 5;
    const int awBase = rA * AW + qA * 4;
    const int bwBase = rB * AW + hB * 8;

    const float mrow = smM[rA];
    const float ivr  = smI[rA];
    const int   srow = mBase + rA;
    const int   cbT  = qA * 8;

    SmemT3* buf0 = (SmemT3*)smraw;
    SmemT3* buf1 = (SmemT3*)(smraw + sizeof(SmemT3));
    const uint32_t b0 = s2u(buf0);

    float4 va[2], vb[4];
    va[0] = *(const float4*)(Ap);
    va[1] = *(const float4*)(Ap + 4);
    #pragma unroll
    for (int j = 0; j < 4; j++) vb[j] = *(const float4*)(Bp + j * 4);
    {   // transform chunk 0
        float* f = (float*)va;
        #pragma unroll
        for (int j = 0; j < 8; j++) {
            int col = cbT + j;
            f[j] = (col <= srow) ? expf(f[j] - mrow) * ivr : 0.f;
        }
    }
    cvt_store3(*buf0, awBase, bwBase, va, vb);
    if (nch > 1) {
        va[0] = *(const float4*)(Ap + 32);
        va[1] = *(const float4*)(Ap + 36);
        #pragma unroll
        for (int j = 0; j < 4; j++) vb[j] = *(const float4*)(Bp + 32 + j * 4);
    }
    __syncthreads();

    for (int t = 0; t < nch; t++) {
        const uint32_t co = b0 + (uint32_t)((t & 1) * (int)sizeof(SmemT3));
        const uint32_t aHiB = co, aLoB = co + 5120;
        const uint32_t bHiB = co + 10240, bLoB = co + 20480;
        mma_step3(aHiB, aLoB, bHiB, bLoB, 0, wm, wn, lane, acc);
        mma_step3(aHiB, aLoB, bHiB, bLoB, 1, wm, wn, lane, acc);
        if (t + 1 < nch) {
            {   // transform chunk t+1 (held in va)
                int cb = (t + 1) * 32 + cbT;
                float* f = (float*)va;
                #pragma unroll
                for (int j = 0; j < 8; j++) {
                    int col = cb + j;
                    f[j] = (col <= srow) ? expf(f[j] - mrow) * ivr : 0.f;
                }
            }
            SmemT3& nxt = ((t + 1) & 1) ? *buf1 : *buf0;
            cvt_store3(nxt, awBase, bwBase, va, vb);
            if (t + 2 < nch) {
                va[0] = *(const float4*)(Ap + (t+2)*32);
                va[1] = *(const float4*)(Ap + (t+2)*32 + 4);
                #pragma unroll
                for (int j = 0; j < 4; j++)
                    vb[j] = *(const float4*)(Bp + (t+2)*32 + j*4);
            }
        }
        __syncthreads();
    }
}

// ================= EXPERT core: fp16 single-pass, fp16 A operand =============
struct SmemT1 {
    uint32_t Ah[64*AW];
    uint32_t Bh[128*AW];
};  // 15360 bytes
#define DSMEM1 (2 * (int)sizeof(SmemT1))   // 30720
#define DSMEM_MID (DSMEM1 + 64*TW*4)       // + 33792 stage = 64512

__device__ __forceinline__ uint32_t pack_h2(float a, float b) {
    __half2 h = __floats2half2_rn(a, b);
    return *reinterpret_cast<uint32_t*>(&h);
}

__device__ __forceinline__ void mma_step1(uint32_t aB, uint32_t bB,
                                          int ks, int wm, int wn, int lane,
                                          float (&acc)[8][4]) {
    const int kw = ks * 8;
    const int r = lane & 7, sub = lane >> 3;
    uint32_t ah[2][4], bh[2][4];
    #pragma unroll
    for (int mt = 0; mt < 2; mt++) {
        uint32_t off = (uint32_t)(((wm*32 + mt*16 + r + (sub&1)*8) * AW
                                   + kw + (sub>>1)*4) * 4);
        ldsm4(ah[mt], aB + off);
    }
    #pragma unroll
    for (int p = 0; p < 2; p++) {
        uint32_t off = (uint32_t)(((wn*32 + p*16 + r + (sub>>1)*8) * AW
                                   + kw + (sub&1)*4) * 4);
        ldsm4(bh[p], bB + off);
    }
    #pragma unroll
    for (int mt = 0; mt < 2; mt++)
        #pragma unroll
        for (int nt = 0; nt < 4; nt++) {
            uint32_t bh2[2] = { bh[nt>>1][(nt&1)*2], bh[nt>>1][(nt&1)*2+1] };
            mma_fp(acc[mt*4+nt], ah[mt], bh2);
        }
}

// A is fp16 in global (no A conversion); B fp32 -> fp16 on the fly.
__device__ __forceinline__ void mma_gemm1h(
    char* smraw,
    const __half* __restrict__ A, int lda, const int* rowTok, int mBase,
    const float* __restrict__ B, int ldb, int nBase, int K,
    float (&acc)[8][4])
{
    const int tid  = threadIdx.x;
    const int lane = tid & 31, wid = tid >> 5;
    const int wm = wid >> 2, wn = wid & 3;

    const int rA = tid >> 2, qA = tid & 3;          // A: 64 rows x 8 halves
    const int rB = tid >> 1, hB = tid & 1;          // B: 128 rows x 16 floats
    const int rowA = rowTok ? rowTok[rA] : (mBase + rA);
    const __half* Ap = A + (size_t)rowA * lda + qA * 8;
    const float*  Bp = B + (size_t)(nBase + rB) * ldb + hB * 16;

    const int nch = K >> 5;
    const int awBase = rA * AW + qA * 4;
    const int bwBase = rB * AW + hB * 8;

    SmemT1* buf0 = (SmemT1*)smraw;
    SmemT1* buf1 = (SmemT1*)(smraw + sizeof(SmemT1));
    const uint32_t b0 = s2u(buf0);

    uint4 va; float4 vb[4];
    va = *(const uint4*)Ap;
    #pragma unroll
    for (int j = 0; j < 4; j++) vb[j] = *(const float4*)(Bp + j * 4);
    {
        SmemT1& s = *buf0;
        *(uint4*)&s.Ah[awBase] = va;
        #pragma unroll
        for (int j = 0; j < 4; j++) {
            uint32_t h0 = pack_h2(vb[j].x, vb[j].y);
            uint32_t h1 = pack_h2(vb[j].z, vb[j].w);
            *(uint2*)&s.Bh[bwBase + j*2] = make_uint2(h0, h1);
        }
    }
    if (nch > 1) {
        va = *(const uint4*)(Ap + 32);
        #pragma unroll
        for (int j = 0; j < 4; j++) vb[j] = *(const float4*)(Bp + 32 + j * 4);
    }
    __syncthreads();

    for (int t = 0; t < nch; t++) {
        const uint32_t co = b0 + (uint32_t)((t & 1) * (int)sizeof(SmemT1));
        const uint32_t aB = co, bB = co + 5120;
        mma_step1(aB, bB, 0, wm, wn, lane, acc);
        mma_step1(aB, bB, 1, wm, wn, lane, acc);
        if (t + 1 < nch) {
            SmemT1& nxt = ((t + 1) & 1) ? *buf1 : *buf0;
            *(uint4*)&nxt.Ah[awBase] = va;
            #pragma unroll
            for (int j = 0; j < 4; j++) {
                uint32_t h0 = pack_h2(vb[j].x, vb[j].y);
                uint32_t h1 = pack_h2(vb[j].z, vb[j].w);
                *(uint2*)&nxt.Bh[bwBase + j*2] = make_uint2(h0, h1);
            }
            if (t + 2 < nch) {
                va = *(const uint4*)(Ap + (t+2)*32);
                #pragma unroll
                for (int j = 0; j < 4; j++)
                    vb[j] = *(const float4*)(Bp + (t+2)*32 + j*4);
            }
        }
        __syncthreads();
    }
}

// ---------------- small utility kernels --------------------------------------
__global__ void rmsnorm_kernel(const float* __restrict__ x,
                               const float* __restrict__ w,
                               float* __restrict__ out) {
    if (blockIdx.x == 0 && threadIdx.x < NE) g_ecnt[threadIdx.x] = 0;
    int row = blockIdx.x;
    const float* xr = x + (size_t)row * DIM;
    float ss = 0.f;
    for (int i = threadIdx.x; i < DIM; i += 256) { float v = xr[i]; ss += v * v; }
    __shared__ float red[256];
    red[threadIdx.x] = ss; __syncthreads();
    for (int st = 128; st > 0; st >>= 1) {
        if (threadIdx.x < st) red[threadIdx.x] += red[threadIdx.x + st];
        __syncthreads();
    }
    float rstd = rsqrtf(red[0] / (float)DIM + EPS);
    for (int i = threadIdx.x; i < DIM; i += 256)
        out[(size_t)row * DIM + i] = xr[i] * rstd * w[i];
}

// fused rmsnorm2 + router: hn (fp16 for experts) + top-8 scatter
__global__ void hn_router_kernel(const float* __restrict__ h,
                                 const float* __restrict__ w,
                                 const float* __restrict__ rw)
{
    int t = blockIdx.x, tid = threadIdx.x;   // 128 threads
    __shared__ float hrow[DIM];
    __shared__ float red[128];
    __shared__ float logits[NE];
    const float* hr = h + (size_t)t * DIM;
    float ss = 0.f;
    for (int i = tid; i < DIM; i += 128) { float v = hr[i]; ss += v * v; }
    red[tid] = ss; __syncthreads();
    for (int st = 64; st > 0; st >>= 1) {
        if (tid < st) red[tid] += red[tid + st];
        __syncthreads();
    }
    float rstd = rsqrtf(red[0] / (float)DIM + EPS);
    for (int i = tid; i < DIM; i += 128) {
        float hn = hr[i] * rstd * w[i];
        hrow[i] = hn;
        g_hn16[(size_t)t * DIM + i] = __float2half(hn);
    }
    __syncthreads();
    if (tid < NE) {
        const float* r = rw + (size_t)tid * DIM;
        float acc = 0.f;
        for (int i = 0; i < DIM; i++) acc += hrow[i] * r[i];
        logits[tid] = acc;
    }
    __syncthreads();
    if (tid == 0) {
        float m = -1e30f;
        for (int e = 0; e < NE; e++) m = fmaxf(m, logits[e]);
        float pr[NE]; float sum = 0.f;
        for (int e = 0; e < NE; e++) { pr[e] = expf(logits[e] - m); sum += pr[e]; }
        float invs = 1.f / sum;
        for (int e = 0; e < NE; e++) pr[e] *= invs;
        int   ti[TOPK]; float tw[TOPK]; float wsum = 0.f;
        for (int kk = 0; kk < TOPK; kk++) {
            int best = 0; float bv = -1.f;
            for (int e = 0; e < NE; e++) if (pr[e] > bv) { bv = pr[e]; best = e; }
            ti[kk] = best; tw[kk] = bv; pr[best] = -2.f; wsum += bv;
        }
        float inv = 1.f / (wsum + 1e-20f);
        for (int kk = 0; kk < TOPK; kk++) {
            int e = ti[kk];
            int pos = atomicAdd(&g_ecnt[e], 1);
            g_etok[e * S + pos] = t;
            g_ew  [e * S + pos] = tw[kk] * inv;
        }
    }
}

// ================== trunk GEMM kernels (bf16 3-pass) ==========================

// QKV: grid (40, 8). q/k heads: fused per-head RMSNorm+RoPE epilogue.
__global__ __launch_bounds__(256) void qkv_kernel(
    const float* __restrict__ xn, const float* __restrict__ wq,
    const float* __restrict__ wk, const float* __restrict__ wv,
    const float* __restrict__ qnw, const float* __restrict__ knw,
    const float* __restrict__ cosp, const float* __restrict__ sinp)
{
    extern __shared__ char smraw[];
    int nt = blockIdx.x, mBase = blockIdx.y * 64;
    const float* B; int head, fam;
    if (nt < H)           { B = wq; head = nt;          fam = 0; }
    else if (nt < H + HK) { B = wk; head = nt - H;      fam = 1; }
    else                  { B = wv; head = nt - H - HK; fam = 2; }
    float acc[8][4] = {};
    mma_gemm3(smraw, xn, DIM, nullptr, mBase, B, DIM, head * HD, DIM, acc);
    int tid = threadIdx.x;
    int lane = tid & 31, wid = tid >> 5;
    int wm = wid >> 2, wn = wid & 3;

    if (fam == 2) {   // V: plain transposed store
        float* o = g_vtT + (size_t)head*HD*S;
        #pragma unroll
        for (int mt = 0; mt < 2; mt++)
            #pragma unroll
            for (int ntl = 0; ntl < 4; ntl++) {
                int r0  = mBase + wm*32 + mt*16 + (lane>>2);
                int col = wn*32 + ntl*8 + (lane&3)*2;
                float* a = acc[mt*4+ntl];
                o[(size_t)col*S     + r0]     = a[0];
                o[(size_t)(col+1)*S + r0]     = a[1];
                o[(size_t)col*S     + r0 + 8] = a[2];
                o[(size_t)(col+1)*S + r0 + 8] = a[3];
            }
        return;
    }

    // q/k: stage tile, per-row rmsnorm, rope, store.
    float* tile = (float*)smraw;   // 64 x TW floats (GEMM buffers are dead)
    #pragma unroll
    for (int mt = 0; mt < 2; mt++)
        #pragma unroll
        for (int ntl = 0; ntl < 4; ntl++) {
            int r  = wm*32 + mt*16 + (lane>>2);
            int c  = wn*32 + ntl*8 + (lane&3)*2;
            float* a = acc[mt*4+ntl];
            tile[r*TW + c] = a[0];     tile[r*TW + c + 1] = a[1];
            tile[(r+8)*TW + c] = a[2]; tile[(r+8)*TW + c + 1] = a[3];
        }
    __syncthreads();

    const float* w = (fam == 0) ? qnw : knw;
    int row = tid >> 2, part = tid & 3;         // 4 threads per row
    float ss = 0.f;
    #pragma unroll
    for (int i = 0; i < 32; i++) {
        float v = tile[row*TW + part*32 + i];
        ss += v * v;
    }
    ss += __shfl_xor_sync(0xffffffffu, ss, 1);
    ss += __shfl_xor_sync(0xffffffffu, ss, 2);
    float rstd = rsqrtf(ss / (float)HD + EPS);
    #pragma unroll
    for (int i = 0; i < 32; i++) {
        int d = part*32 + i;
        tile[row*TW + d] *= rstd * w[d];
    }
    __syncthreads();

    int s = mBase + row;
    float* o = ((fam == 0) ? g_qt + (size_t)head*S*HD
                           : g_kt + (size_t)head*S*HD) + (size_t)s * HD;
    const float* cp = cosp + (size_t)s * HD;
    const float* sp = sinp + (size_t)s * HD;
    #pragma unroll
    for (int i = 0; i < 32; i++) {
        int d = part*32 + i;
        float n = tile[row*TW + d];
        float rot = (d < 64) ? -tile[row*TW + d + 64] : tile[row*TW + d - 64];
        o[d] = n * cp[d] + rot * sp[d];
    }
}

// scores: grid (4, 8, 32). Skip fully-masked tiles. Raw scaled logits out.
__global__ __launch_bounds__(256) void scores_kernel()
{
    int h = blockIdx.z, mBase = blockIdx.y * 64, nBase = blockIdx.x * 128;
    if (nBase > mBase + 63) return;
    extern __shared__ char smraw[];
    int kvh = h / GRP;
    float acc[8][4] = {};
    mma_gemm3(smraw, g_qt + (size_t)h * S * HD, HD, nullptr, mBase,
              g_kt + (size_t)kvh * S * HD, HD, nBase, HD, acc);
    const float alpha = 0.08838834764831845f;   // 1/sqrt(128)
    float* C = g_scores + (size_t)h * S * S;
    int lane = threadIdx.x & 31, wid = threadIdx.x >> 5;
    int wm = wid >> 2, wn = wid & 3;
    #pragma unroll
    for (int mt = 0; mt < 2; mt++)
        #pragma unroll
        for (int ntl = 0; ntl < 4; ntl++) {
            int r0  = mBase + wm*32 + mt*16 + (lane>>2);
            int col = nBase + wn*32 + ntl*8 + (lane&3)*2;
            float* a = acc[mt*4+ntl];
            *(float2*)&C[(size_t)r0*S + col]     = make_float2(a[0]*alpha, a[1]*alpha);
            *(float2*)&C[(size_t)(r0+8)*S + col] = make_float2(a[2]*alpha, a[3]*alpha);
        }
}

// pv: grid (1, 8, 32). Fused softmax: per-row m/sum prologue, exp in A-convert.
__global__ __launch_bounds__(256) void pv_kernel()
{
    extern __shared__ char smraw[];
    int h = blockIdx.z, mBase = blockIdx.y * 64;
    int kvh = h / GRP;
    const float* SC = g_scores + (size_t)h * S * S;
    float* smM = (float*)(smraw + DSMEM3);
    float* smI = smM + 64;
    int tid = threadIdx.x;
    {
        int row = tid >> 2, p = tid & 3;
        int srow = mBase + row;
        const float* sr = SC + (size_t)srow * S;
        float m = -1e30f;
        for (int c = p; c <= srow; c += 4) m = fmaxf(m, sr[c]);
        m = fmaxf(m, __shfl_xor_sync(0xffffffffu, m, 1));
        m = fmaxf(m, __shfl_xor_sync(0xffffffffu, m, 2));
        float sum = 0.f;
        for (int c = p; c <= srow; c += 4) sum += expf(sr[c] - m);
        sum += __shfl_xor_sync(0xffffffffu, sum, 1);
        sum += __shfl_xor_sync(0xffffffffu, sum, 2);
        if (p == 0) { smM[row] = m; smI[row] = 1.f / sum; }
    }
    __syncthreads();

    float acc[8][4] = {};
    mma_gemm3sm(smraw, SC, S, mBase, g_vtT + (size_t)kvh * HD * S, S, S,
                smM, smI, acc);
    int lane = tid & 31, wid = tid >> 5;
    int wm = wid >> 2, wn = wid & 3;
    #pragma unroll
    for (int mt = 0; mt < 2; mt++)
        #pragma unroll
        for (int ntl = 0; ntl < 4; ntl++) {
            int r0  = mBase + wm*32 + mt*16 + (lane>>2);
            int col = h*HD + wn*32 + ntl*8 + (lane&3)*2;
            float* a = acc[mt*4+ntl];
            *(float2*)&g_attn[(size_t)r0*NQK + col]     = make_float2(a[0], a[1]);
            *(float2*)&g_attn[(size_t)(r0+8)*NQK + col] = make_float2(a[2], a[3]);
        }
}

// wo: grid (16, 8). out = attn @ wo^T + x  -> d_out
__global__ __launch_bounds__(256) void wo_kernel(
    const float* __restrict__ wo_w, const float* __restrict__ x,
    float* __restrict__ out)
{
    extern __shared__ char smraw[];
    int nBase = blockIdx.x * 128, mBase = blockIdx.y * 64;
    float acc[8][4] = {};
    mma_gemm3(smraw, g_attn, NQK, nullptr, mBase, wo_w, NQK, nBase, NQK, acc);
    int lane = threadIdx.x & 31, wid = threadIdx.x >> 5;
    int wm = wid >> 2, wn = wid & 3;
    #pragma unroll
    for (int mt = 0; mt < 2; mt++)
        #pragma unroll
        for (int ntl = 0; ntl < 4; ntl++) {
            int r0  = mBase + wm*32 + mt*16 + (lane>>2);
            int col = nBase + wn*32 + ntl*8 + (lane&3)*2;
            float* a = acc[mt*4+ntl];
            size_t i0 = (size_t)r0*DIM + col, i1 = (size_t)(r0+8)*DIM + col;
            float2 x0 = *(const float2*)&x[i0], x1 = *(const float2*)&x[i1];
            *(float2*)&out[i0] = make_float2(a[0] + x0.x, a[1] + x0.y);
            *(float2*)&out[i1] = make_float2(a[2] + x1.x, a[3] + x1.y);
        }
}

// ================== expert GEMM kernels (fp16, fp16 A) ========================

// moe mid: grid (6, 8, 64). Per block: gate GEMM -> stage, up GEMM, silu*u.
__global__ __launch_bounds__(256) void moe_mid_kernel(
    const float* __restrict__ gate_w, const float* __restrict__ up_w)
{
    int e = blockIdx.z;
    int Me = g_ecnt[e];
    int rowBase = blockIdx.y * 64;
    if (rowBase >= Me) return;
    extern __shared__ char smraw[];
    __shared__ int tok[64];
    if (threadIdx.x < 64)
        tok[threadIdx.x] = g_etok[e * S + min(rowBase + (int)threadIdx.x, Me - 1)];
    __syncthreads();
    int nBase = blockIdx.x * 128;

    int lane = threadIdx.x & 31, wid = threadIdx.x >> 5;
    int wm = wid >> 2, wn = wid & 3;
    float* stage = (float*)(smraw + DSMEM1);   // 64 x TW floats

    // pass 1: gate
    float acc[8][4] = {};
    mma_gemm1h(smraw, g_hn16, DIM, tok, 0, gate_w + (size_t)e * FF * DIM,
               DIM, nBase, DIM, acc);
    #pragma unroll
    for (int mt = 0; mt < 2; mt++)
        #pragma unroll
        for (int ntl = 0; ntl < 4; ntl++) {
            int r = wm*32 + mt*16 + (lane>>2);
            int c = wn*32 + ntl*8 + (lane&3)*2;
            float* a = acc[mt*4+ntl];
            stage[r*TW + c] = a[0];     stage[r*TW + c + 1] = a[1];
            stage[(r+8)*TW + c] = a[2]; stage[(r+8)*TW + c + 1] = a[3];
        }
    // no sync needed: each thread re-reads only its own staged values, and the
    // stage area is disjoint from the GEMM buffers the second pass uses.

    // pass 2: up (reuse acc)
    #pragma unroll
    for (int i = 0; i < 8; i++)
        #pragma unroll
        for (int j = 0; j < 4; j++) acc[i][j] = 0.f;
    mma_gemm1h(smraw, g_hn16, DIM, tok, 0, up_w + (size_t)e * FF * DIM,
               DIM, nBase, DIM, acc);

    // epilogue: mid = silu(gate) * up  (stored fp16)
    #pragma unroll
    for (int mt = 0; mt < 2; mt++)
        #pragma unroll
        for (int ntl = 0; ntl < 4; ntl++) {
            int lr  = wm*32 + mt*16 + (lane>>2);
            int lc  = wn*32 + ntl*8 + (lane&3)*2;
            int col = nBase + lc;
            float* a = acc[mt*4+ntl];
            int s0 = rowBase + lr, s1 = s0 + 8;
            if (s0 < Me) {
                float gg0 = stage[lr*TW + lc], gg1 = stage[lr*TW + lc + 1];
                float m0 = gg0 / (1.f + expf(-gg0)) * a[0];
                float m1 = gg1 / (1.f + expf(-gg1)) * a[1];
                *(__half2*)&g_mid[(size_t)(e*S + s0)*FF + col] = __floats2half2_rn(m0, m1);
            }
            if (s1 < Me) {
                float gg2 = stage[(lr+8)*TW + lc], gg3 = stage[(lr+8)*TW + lc + 1];
                float m2 = gg2 / (1.f + expf(-gg2)) * a[2];
                float m3 = gg3 / (1.f + expf(-gg3)) * a[3];
                *(__half2*)&g_mid[(size_t)(e*S + s1)*FF + col] = __floats2half2_rn(m2, m3);
            }
        }
}

// moe down: grid (16, 8, 64). Weighted atomic scatter onto out.
__global__ __launch_bounds__(256) void moe_down_kernel(
    const float* __restrict__ down_w, float* __restrict__ out)
{
    int e = blockIdx.z;
    int Me = g_ecnt[e];
    int rowBase = blockIdx.y * 64;
    if (rowBase >= Me) return;
    extern __shared__ char smraw[];
    __shared__ int tok[64];
    __shared__ float wts[64];
    if (threadIdx.x < 64) {
        int sl = min(rowBase + (int)threadIdx.x, Me - 1);
        tok[threadIdx.x] = g_etok[e * S + sl];
        wts[threadIdx.x] = g_ew  [e * S + sl];
    }
    __syncthreads();
    int nBase = blockIdx.x * 128;
    float acc[8][4] = {};
    mma_gemm1h(smraw, g_mid + (size_t)e * S * FF, FF, nullptr, rowBase,
               down_w + (size_t)e * DIM * FF, FF, nBase, FF, acc);
    int lane = threadIdx.x & 31, wid = threadIdx.x >> 5;
    int wm = wid >> 2, wn = wid & 3;
    #pragma unroll
    for (int mt = 0; mt < 2; mt++)
        #pragma unroll
        for (int ntl = 0; ntl < 4; ntl++) {
            int lr  = wm*32 + mt*16 + (lane>>2);
            int col = nBase + wn*32 + ntl*8 + (lane&3)*2;
            float* a = acc[mt*4+ntl];
            int s0 = rowBase + lr, s1 = s0 + 8;
            if (s0 < Me) {
                int t = tok[lr]; float w = wts[lr];
                atomicAdd(&out[(size_t)t*DIM + col],     a[0]*w);
                atomicAdd(&out[(size_t)t*DIM + col + 1], a[1]*w);
            }
            if (s1 < Me) {
                int t = tok[lr+8]; float w = wts[lr+8];
                atomicAdd(&out[(size_t)t*DIM + col],     a[2]*w);
                atomicAdd(&out[(size_t)t*DIM + col + 1], a[3]*w);
            }
        }
}

// ---------------- launch ------------------------------------------------------
extern "C" void kernel_launch(void* const* d_in, const int* in_sizes, int n_in,
                              void* d_out, int out_size)
{
    const float* x    = (const float*)d_in[0];
    const float* cosp = (const float*)d_in[1];
    const float* sinp = (const float*)d_in[2];
    const float* n1w  = (const float*)d_in[3];
    const float* wq   = (const float*)d_in[4];
    const float* wk   = (const float*)d_in[5];
    const float* wv   = (const float*)d_in[6];
    const float* wo_w = (const float*)d_in[7];
    const float* qnw  = (const float*)d_in[8];
    const float* knw  = (const float*)d_in[9];
    const float* n2w  = (const float*)d_in[10];
    const float* rw   = (const float*)d_in[11];
    const float* gw   = (const float*)d_in[12];
    const float* uw   = (const float*)d_in[13];
    const float* dw   = (const float*)d_in[14];
    float* out = (float*)d_out;

    cudaFuncSetAttribute(qkv_kernel,      cudaFuncAttributeMaxDynamicSharedMemorySize, DSMEM3);
    cudaFuncSetAttribute(scores_kernel,   cudaFuncAttributeMaxDynamicSharedMemorySize, DSMEM3);
    cudaFuncSetAttribute(pv_kernel,       cudaFuncAttributeMaxDynamicSharedMemorySize, DSMEM_PV);
    cudaFuncSetAttribute(wo_kernel,       cudaFuncAttributeMaxDynamicSharedMemorySize, DSMEM3);
    cudaFuncSetAttribute(moe_mid_kernel,  cudaFuncAttributeMaxDynamicSharedMemorySize, DSMEM_MID);
    cudaFuncSetAttribute(moe_down_kernel, cudaFuncAttributeMaxDynamicSharedMemorySize, DSMEM1);

    float* xn;
    cudaGetSymbolAddress((void**)&xn, g_xn);

    rmsnorm_kernel<<<S, 256>>>(x, n1w, xn);           // also zeroes g_ecnt
    qkv_kernel<<<dim3(H + 2*HK, S/64), 256, DSMEM3>>>(xn, wq, wk, wv,
                                                      qnw, knw, cosp, sinp);
    scores_kernel<<<dim3(S/128, S/64, H), 256, DSMEM3>>>();
    pv_kernel<<<dim3(1, S/64, H), 256, DSMEM_PV>>>();
    wo_kernel<<<dim3(DIM/128, S/64), 256, DSMEM3>>>(wo_w, x, out);
    hn_router_kernel<<<S, 128>>>(out, n2w, rw);
    moe_mid_kernel<<<dim3(6, S/64, NE), 256, DSMEM_MID>>>(gw, uw);
    moe_down_kernel<<<dim3(DIM/128, S/64, NE), 256, DSMEM1>>>(dw, out);
}